// round 10
// baseline (speedup 1.0000x reference)
#include <cuda_runtime.h>
#include <cuda_bf16.h>
#include <math.h>
#include <stdint.h>

#define TT   32768
#define CC   512
#define EE   8
#define HH   16
#define BB   8
#define NNN  4096
#define FIXCAP 8192

// ---------------- scratch (static device globals; no allocation) -------------
__device__ float g_h[(size_t)TT * CC];     // gate hidden, 64MB
__device__ float g_h1[(size_t)TT * 128];   // expert hidden (all experts), 16MB
__device__ int   g_re[TT * 2];
__device__ float g_rw[TT * 2];
__device__ float g_sum[CC];
__device__ float g_sumsq[CC];
__device__ float g_usage[EE];
__device__ int   g_nfix;
__device__ int   g_fix[FIXCAP];
__device__ __align__(16) __nv_bfloat16 g_xh[(size_t)TT * CC];
__device__ __align__(16) __nv_bfloat16 g_xl[(size_t)TT * CC];
__device__ __align__(16) __nv_bfloat16 g_wh[CC * CC];
__device__ __align__(16) __nv_bfloat16 g_wl[CC * CC];
__device__ __align__(16) __nv_bfloat16 g_w1h[128 * CC];   // W1cat^T [n=e*16+h][k=c]
__device__ __align__(16) __nv_bfloat16 g_w1l[128 * CC];
__device__ __align__(16) __nv_bfloat16 g_w2h[CC * 128];   // W2cat^T [n=c][k=e*16+h]
__device__ __align__(16) __nv_bfloat16 g_w2l[CC * 128];
__device__ __align__(16) __nv_bfloat16 g_ah[(size_t)TT * 128];  // h1scaled hi
__device__ __align__(16) __nv_bfloat16 g_al[(size_t)TT * 128];  // h1scaled lo

// ---------------- PTX helpers -------------------------------------------------
__device__ __forceinline__ uint32_t smem_u32(const void* p) {
    uint32_t a;
    asm("{ .reg .u64 t; cvta.to.shared.u64 t, %1; cvt.u32.u64 %0, t; }" : "=r"(a) : "l"(p));
    return a;
}
__device__ __forceinline__ void ldm4(uint32_t* r, uint32_t a) {
    asm volatile("ldmatrix.sync.aligned.m8n8.x4.shared.b16 {%0,%1,%2,%3}, [%4];"
                 : "=r"(r[0]), "=r"(r[1]), "=r"(r[2]), "=r"(r[3]) : "r"(a));
}
__device__ __forceinline__ void mma16816(float* d, const uint32_t* a,
                                         uint32_t b0, uint32_t b1) {
    asm volatile(
        "mma.sync.aligned.m16n8k16.row.col.f32.bf16.bf16.f32 "
        "{%0,%1,%2,%3}, {%4,%5,%6,%7}, {%8,%9}, {%0,%1,%2,%3};"
        : "+f"(d[0]), "+f"(d[1]), "+f"(d[2]), "+f"(d[3])
        : "r"(a[0]), "r"(a[1]), "r"(a[2]), "r"(a[3]), "r"(b0), "r"(b1));
}
#define CP16(dst, src) asm volatile("cp.async.cg.shared.global [%0], [%1], 16;" ::"r"(dst), "l"(src) : "memory")
#define CPCOMMIT()     asm volatile("cp.async.commit_group;" ::: "memory")
#define CPWAIT(n)      asm volatile("cp.async.wait_group %0;" ::"n"(n) : "memory")

// ---------------- zero accumulators ------------------------------------------
__global__ void k_zero() {
    int i = threadIdx.x;
    if (i < CC) { g_sum[i] = 0.f; g_sumsq[i] = 0.f; }
    if (i < EE) g_usage[i] = 0.f;
    if (i == 0) g_nfix = 0;
}

// ---------------- bf16 splits --------------------------------------------------
__global__ __launch_bounds__(256) void k_split(const float* __restrict__ x,
                                               const float* __restrict__ wg1) {
    size_t i4 = (size_t)blockIdx.x * 256 + threadIdx.x;
    const size_t nx = (size_t)TT * CC / 4, nw = (size_t)CC * CC / 4;
    const float* s; __nv_bfloat16 *dh, *dl; size_t o;
    if (i4 < nx)           { s = x;   o = i4;      dh = g_xh; dl = g_xl; }
    else if (i4 < nx + nw) { s = wg1; o = i4 - nx; dh = g_wh; dl = g_wl; }
    else return;
    float4 v = ((const float4*)s)[o];
    float a[4] = {v.x, v.y, v.z, v.w};
    unsigned hh[4], ll[4];
#pragma unroll
    for (int i = 0; i < 4; i++) {
        __nv_bfloat16 hb = __float2bfloat16(a[i]);
        __nv_bfloat16 lb = __float2bfloat16(a[i] - __bfloat162float(hb));
        hh[i] = ((__nv_bfloat16_raw)hb).x;
        ll[i] = ((__nv_bfloat16_raw)lb).x;
    }
    uint2 ph = {hh[0] | (hh[1] << 16), hh[2] | (hh[3] << 16)};
    uint2 pl = {ll[0] | (ll[1] << 16), ll[2] | (ll[3] << 16)};
    ((uint2*)dh)[o] = ph;
    ((uint2*)dl)[o] = pl;
}

// expert weight repack + split
__global__ __launch_bounds__(256) void k_split2(const float* __restrict__ w1,
                                                const float* __restrict__ w2) {
    int idx = blockIdx.x * 256 + threadIdx.x;
    if (idx < 65536) {
        int e = idx >> 13, r = idx & 8191, c = r >> 4, h = r & 15;
        float v = w1[idx];
        __nv_bfloat16 hb = __float2bfloat16(v);
        __nv_bfloat16 lb = __float2bfloat16(v - __bfloat162float(hb));
        int n = e * 16 + h;
        g_w1h[n * CC + c] = hb;
        g_w1l[n * CC + c] = lb;
    } else if (idx < 131072) {
        int j = idx - 65536;
        int e = j >> 13, r = j & 8191, h = r >> 9, c = r & 511;
        float v = w2[j];
        __nv_bfloat16 hb = __float2bfloat16(v);
        __nv_bfloat16 lb = __float2bfloat16(v - __bfloat162float(hb));
        int n = e * 16 + h;
        g_w2h[c * 128 + n] = hb;
        g_w2l[c * 128 + n] = lb;
    }
}

// ---------------- gate GEMM1 (HMMA, 2-term, cp.async 2-stage) -----------------
#define STG 49152
#define GSMEM (2 * STG)

__global__ __launch_bounds__(256, 2) void k_gemm(const float* __restrict__ bg1) {
    extern __shared__ char smc[];
    uint32_t sb = smem_u32(smc);
    int tid = threadIdx.x;
    int n0 = blockIdx.x * 128, m0 = blockIdx.y * 128;
    int warp = tid >> 5, lane = tid & 31;
    int wm = warp >> 1, wn = warp & 1;

    const __nv_bfloat16* xs  = g_xh + (size_t)m0 * CC;
    const __nv_bfloat16* whs = g_wh + (size_t)n0 * CC;
    const __nv_bfloat16* wls = g_wl + (size_t)n0 * CC;

    float acc[2][8][4];
#pragma unroll
    for (int i = 0; i < 2; i++)
#pragma unroll
        for (int j = 0; j < 8; j++)
#pragma unroll
            for (int q = 0; q < 4; q++) acc[i][j][q] = 0.f;

    int li = lane & 7, lm = lane >> 3;
    int a_row = (lm & 1) * 8 + li, a_cb = (lm >> 1) * 16;
    int b_row = (lm >> 1) * 8 + li, b_cb = (lm & 1) * 16;

#define LOADSTAGE(S, K0) do {                                                   \
        uint32_t sbs = sb + (S) * STG;                                          \
        const __nv_bfloat16* srcs[3] = {xs, whs, wls};                          \
        _Pragma("unroll")                                                       \
        for (int tt = 0; tt < 3; tt++) {                                        \
            const __nv_bfloat16* src = srcs[tt];                                \
            _Pragma("unroll")                                                   \
            for (int it = 0; it < 4; it++) {                                    \
                int idx = tid + it * 256;                                       \
                int r = idx >> 3, c16 = idx & 7;                                \
                const void* g = src + (size_t)r * CC + (K0) + c16 * 8;          \
                uint32_t bo = (uint32_t)((r << 7) | (c16 << 4));                \
                bo ^= (bo >> 3) & 0x70;                                         \
                CP16(sbs + tt * 16384 + bo, g);                                 \
            }                                                                   \
        }                                                                       \
    } while (0)

    LOADSTAGE(0, 0);
    CPCOMMIT();

    for (int kc = 0; kc < 8; kc++) {
        int s = kc & 1;
        if (kc < 7) {
            LOADSTAGE(s ^ 1, (kc + 1) * 64);
            CPCOMMIT();
            CPWAIT(1);
        } else {
            CPWAIT(0);
        }
        __syncthreads();

        uint32_t abase = sb + s * STG;
#pragma unroll
        for (int tp = 0; tp < 2; tp++) {
            uint32_t bbase = abase + 16384 + tp * 16384;
#pragma unroll
            for (int ks = 0; ks < 4; ks++) {
                int kb = ks * 32;
                uint32_t af[2][4];
#pragma unroll
                for (int mi = 0; mi < 2; mi++) {
                    int r = wm * 32 + mi * 16 + a_row;
                    uint32_t cb = (uint32_t)(kb + a_cb);
                    ldm4(af[mi], abase + (r << 7) + (cb ^ ((r & 7) << 4)));
                }
                uint32_t bfr[4][4];
#pragma unroll
                for (int p = 0; p < 4; p++) {
                    int r = wn * 64 + p * 16 + b_row;
                    uint32_t cb = (uint32_t)(kb + b_cb);
                    ldm4(bfr[p], bbase + (r << 7) + (cb ^ ((r & 7) << 4)));
                }
#pragma unroll
                for (int mi = 0; mi < 2; mi++)
#pragma unroll
                    for (int ni = 0; ni < 8; ni++)
                        mma16816(acc[mi][ni], af[mi],
                                 bfr[ni >> 1][(ni & 1) * 2],
                                 bfr[ni >> 1][(ni & 1) * 2 + 1]);
            }
        }
        __syncthreads();
    }
#undef LOADSTAGE

    int g = lane >> 2, tg = lane & 3;
#pragma unroll
    for (int mi = 0; mi < 2; mi++) {
        int row = m0 + wm * 32 + mi * 16 + g;
#pragma unroll
        for (int ni = 0; ni < 8; ni++) {
            int col = n0 + wn * 64 + ni * 8 + tg * 2;
            float bx = bg1[col], by = bg1[col + 1];
            acc[mi][ni][0] += bx; acc[mi][ni][1] += by;
            acc[mi][ni][2] += bx; acc[mi][ni][3] += by;
            float2 v0 = {acc[mi][ni][0], acc[mi][ni][1]};
            float2 v1 = {acc[mi][ni][2], acc[mi][ni][3]};
            *(float2*)(g_h + (size_t)row * CC + col) = v0;
            *(float2*)(g_h + (size_t)(row + 8) * CC + col) = v1;
        }
    }

    float* ssum = (float*)smc;
    float* ssq  = (float*)(smc + 512);
    if (tid < 128) { ssum[tid] = 0.f; ssq[tid] = 0.f; }
    __syncthreads();
#pragma unroll
    for (int ni = 0; ni < 8; ni++) {
        int colr = wn * 64 + ni * 8 + tg * 2;
        float s0 = 0.f, s1 = 0.f, q0 = 0.f, q1 = 0.f;
#pragma unroll
        for (int mi = 0; mi < 2; mi++) {
            float a0 = acc[mi][ni][0], a1 = acc[mi][ni][1];
            float a2 = acc[mi][ni][2], a3 = acc[mi][ni][3];
            s0 += a0 + a2; s1 += a1 + a3;
            q0 += a0 * a0 + a2 * a2; q1 += a1 * a1 + a3 * a3;
        }
#pragma unroll
        for (int off = 4; off < 32; off <<= 1) {
            s0 += __shfl_xor_sync(0xffffffffu, s0, off);
            s1 += __shfl_xor_sync(0xffffffffu, s1, off);
            q0 += __shfl_xor_sync(0xffffffffu, q0, off);
            q1 += __shfl_xor_sync(0xffffffffu, q1, off);
        }
        if (g == 0) {
            atomicAdd(&ssum[colr], s0); atomicAdd(&ssum[colr + 1], s1);
            atomicAdd(&ssq[colr], q0);  atomicAdd(&ssq[colr + 1], q1);
        }
    }
    __syncthreads();
    if (tid < 128) {
        atomicAdd(&g_sum[n0 + tid], ssum[tid]);
        atomicAdd(&g_sumsq[n0 + tid], ssq[tid]);
    }
}

// ---------------- expert GEMM1: h1all = relu(x @ W1cat + b1) (3-term) --------
// A (xh|xl) double-buffered 2x32KB; B (w1h|w1l) single-buffered 32KB (L2-hot).
// 96KB -> 2 CTAs/SM.
#define ESMEM1 98304

__global__ __launch_bounds__(256, 2) void k_egemm1(const float* __restrict__ b1) {
    extern __shared__ char smc[];
    uint32_t sb = smem_u32(smc);
    int tid = threadIdx.x;
    int m0 = blockIdx.x * 128;
    int warp = tid >> 5, lane = tid & 31;
    int wm = warp >> 1, wn = warp & 1;

    const __nv_bfloat16* ah = g_xh + (size_t)m0 * CC;
    const __nv_bfloat16* al = g_xl + (size_t)m0 * CC;

    float acc[2][8][4];
#pragma unroll
    for (int i = 0; i < 2; i++)
#pragma unroll
        for (int j = 0; j < 8; j++)
#pragma unroll
            for (int q = 0; q < 4; q++) acc[i][j][q] = 0.f;

    int li = lane & 7, lm = lane >> 3;
    int a_row = (lm & 1) * 8 + li, a_cb = (lm >> 1) * 16;
    int b_row = (lm >> 1) * 8 + li, b_cb = (lm & 1) * 16;

#define LOADA1(S, K0) do {                                                      \
        uint32_t sbs = sb + (S) * 32768;                                        \
        const __nv_bfloat16* srcs[2] = {ah, al};                                \
        _Pragma("unroll")                                                       \
        for (int tt = 0; tt < 2; tt++) {                                        \
            const __nv_bfloat16* src = srcs[tt];                                \
            _Pragma("unroll")                                                   \
            for (int it = 0; it < 4; it++) {                                    \
                int idx = tid + it * 256;                                       \
                int r = idx >> 3, c16 = idx & 7;                                \
                const void* g = src + (size_t)r * CC + (K0) + c16 * 8;          \
                uint32_t bo = (uint32_t)((r << 7) | (c16 << 4));                \
                bo ^= (bo >> 3) & 0x70;                                         \
                CP16(sbs + tt * 16384 + bo, g);                                 \
            }                                                                   \
        }                                                                       \
    } while (0)
#define LOADB1(K0) do {                                                         \
        uint32_t sbs = sb + 65536;                                              \
        const __nv_bfloat16* srcs[2] = {g_w1h, g_w1l};                          \
        _Pragma("unroll")                                                       \
        for (int tt = 0; tt < 2; tt++) {                                        \
            const __nv_bfloat16* src = srcs[tt];                                \
            _Pragma("unroll")                                                   \
            for (int it = 0; it < 4; it++) {                                    \
                int idx = tid + it * 256;                                       \
                int r = idx >> 3, c16 = idx & 7;                                \
                const void* g = src + (size_t)r * CC + (K0) + c16 * 8;          \
                uint32_t bo = (uint32_t)((r << 7) | (c16 << 4));                \
                bo ^= (bo >> 3) & 0x70;                                         \
                CP16(sbs + tt * 16384 + bo, g);                                 \
            }                                                                   \
        }                                                                       \
    } while (0)

    LOADB1(0);
    LOADA1(0, 0);
    CPCOMMIT();                 // G0 = B(0)+A(0)
    LOADA1(1, 64);
    CPCOMMIT();                 // G1 = A(1)

    const int aoff[3] = {0, 0, 16384};
    const int boff[3] = {0, 16384, 0};

    for (int kc = 0; kc < 8; kc++) {
        int s = kc & 1;
        if (kc > 0) {
            __syncthreads();                     // compute kc-1 done reading Bs
            LOADB1(kc * 64);
            CPCOMMIT();                          // Gb(kc)
            if (kc < 7) {
                LOADA1(s ^ 1, (kc + 1) * 64);
                CPCOMMIT();                      // Ga(kc+1)
                CPWAIT(1);                       // retires A(kc), Gb(kc)
            } else {
                CPWAIT(0);
            }
        } else {
            CPWAIT(1);                           // retires G0, leaves A(1)
        }
        __syncthreads();

#pragma unroll
        for (int tp = 0; tp < 3; tp++) {
            uint32_t abase = sb + s * 32768 + aoff[tp];
            uint32_t bbase = sb + 65536 + boff[tp];
#pragma unroll
            for (int ks = 0; ks < 4; ks++) {
                int kb = ks * 32;
                uint32_t af[2][4];
#pragma unroll
                for (int mi = 0; mi < 2; mi++) {
                    int r = wm * 32 + mi * 16 + a_row;
                    uint32_t cb = (uint32_t)(kb + a_cb);
                    ldm4(af[mi], abase + (r << 7) + (cb ^ ((r & 7) << 4)));
                }
                uint32_t bfr[4][4];
#pragma unroll
                for (int p = 0; p < 4; p++) {
                    int r = wn * 64 + p * 16 + b_row;
                    uint32_t cb = (uint32_t)(kb + b_cb);
                    ldm4(bfr[p], bbase + (r << 7) + (cb ^ ((r & 7) << 4)));
                }
#pragma unroll
                for (int mi = 0; mi < 2; mi++)
#pragma unroll
                    for (int ni = 0; ni < 8; ni++)
                        mma16816(acc[mi][ni], af[mi],
                                 bfr[ni >> 1][(ni & 1) * 2],
                                 bfr[ni >> 1][(ni & 1) * 2 + 1]);
            }
        }
    }
#undef LOADA1
#undef LOADB1

    int g = lane >> 2, tg = lane & 3;
#pragma unroll
    for (int mi = 0; mi < 2; mi++) {
        int row = m0 + wm * 32 + mi * 16 + g;
#pragma unroll
        for (int ni = 0; ni < 8; ni++) {
            int col = wn * 64 + ni * 8 + tg * 2;
            float bx = b1[col], by = b1[col + 1];
            float2 v0 = {fmaxf(acc[mi][ni][0] + bx, 0.f), fmaxf(acc[mi][ni][1] + by, 0.f)};
            float2 v1 = {fmaxf(acc[mi][ni][2] + bx, 0.f), fmaxf(acc[mi][ni][3] + by, 0.f)};
            *(float2*)(g_h1 + (size_t)row * 128 + col) = v0;
            *(float2*)(g_h1 + (size_t)(row + 8) * 128 + col) = v1;
        }
    }
}

// ---------------- routing: stream h from gmem, warp-per-token ----------------
#define RSTR 516
__global__ __launch_bounds__(256) void k_route(const float* __restrict__ gamma,
                                               const float* __restrict__ beta,
                                               const float* __restrict__ wg2,
                                               const float* __restrict__ bg2) {
    __shared__ float ws[EE * RSTR];
    __shared__ float sc[CC], sh[CC];
    __shared__ float susage[EE];
    __shared__ float sbg2[EE];
    int tid = threadIdx.x, warp = tid >> 5, lane = tid & 31;

    if (tid < EE) { susage[tid] = 0.f; sbg2[tid] = bg2[tid]; }
    for (int c = tid; c < CC; c += 256) {
        float m = g_sum[c] * (1.0f / TT);
        float v = g_sumsq[c] * (1.0f / TT) - m * m;
        float rs = rsqrtf(v + 1e-5f);
        float s = gamma[c] * rs;
        sc[c] = s;
        sh[c] = beta[c] - m * s;
    }
    for (int i4 = tid; i4 < EE * 128; i4 += 256) {
        int e = i4 >> 7, c4 = (i4 & 127) << 2;
        float4 v = *(const float4*)(wg2 + e * CC + c4);
        *(float4*)(ws + e * RSTR + c4) = v;
    }
    __syncthreads();

#pragma unroll 1
    for (int j = 0; j < 4; j++) {
        int t = blockIdx.x * 32 + warp * 4 + j;
        float p[EE];
#pragma unroll
        for (int e = 0; e < EE; e++) p[e] = 0.f;
#pragma unroll 1
        for (int i = 0; i < 4; i++) {
            int c4 = i * 128 + lane * 4;
            float4 v = *(const float4*)(g_h + (size_t)t * CC + c4);
            float4 r;
            r.x = fmaxf(sc[c4 + 0] * v.x + sh[c4 + 0], 0.f);
            r.y = fmaxf(sc[c4 + 1] * v.y + sh[c4 + 1], 0.f);
            r.z = fmaxf(sc[c4 + 2] * v.z + sh[c4 + 2], 0.f);
            r.w = fmaxf(sc[c4 + 3] * v.w + sh[c4 + 3], 0.f);
#pragma unroll
            for (int e = 0; e < EE; e++) {
                float4 w = *(const float4*)(ws + e * RSTR + c4);
                p[e] += r.x * w.x + r.y * w.y + r.z * w.z + r.w * w.w;
            }
        }
#pragma unroll
        for (int e = 0; e < EE; e++)
#pragma unroll
            for (int off = 16; off; off >>= 1)
                p[e] += __shfl_xor_sync(0xffffffffu, p[e], off);

        if (lane == 0) {
            float l[EE];
#pragma unroll
            for (int e = 0; e < EE; e++) l[e] = p[e] + sbg2[e];
            int e0 = 0; float v0 = l[0];
#pragma unroll
            for (int e = 1; e < EE; e++) if (l[e] > v0) { v0 = l[e]; e0 = e; }
            int e1 = -1; float v1 = -1e30f;
#pragma unroll
            for (int e = 0; e < EE; e++) if (e != e0 && l[e] > v1) { v1 = l[e]; e1 = e; }
            float v2 = -1e30f;
#pragma unroll
            for (int e = 0; e < EE; e++) if (e != e0 && e != e1 && l[e] > v2) v2 = l[e];
            float ex = expf(v1 - v0);
            float inv = 1.f / (1.f + ex);
            g_re[t * 2] = e0; g_re[t * 2 + 1] = e1;
            g_rw[t * 2] = inv; g_rw[t * 2 + 1] = ex * inv;
            bool flagged = (v1 - v2) < 2.5e-3f;
            if (flagged) {
                int pos = atomicAdd(&g_nfix, 1);
                if (pos < FIXCAP) g_fix[pos] = t; else flagged = false;
            }
            if (!flagged) {
                atomicAdd(&susage[e0], inv);
                atomicAdd(&susage[e1], ex * inv);
            }
        }
    }
    __syncthreads();
    if (tid < EE) atomicAdd(&g_usage[tid], susage[tid]);
}

// ---------------- exact fp32 recompute for near-tie tokens -------------------
__global__ __launch_bounds__(256) void k_fix(const float* __restrict__ x,
                                             const float* __restrict__ wg1,
                                             const float* __restrict__ gamma,
                                             const float* __restrict__ beta,
                                             const float* __restrict__ wg2,
                                             const float* __restrict__ bg2) {
    __shared__ float xr[CC], rr[CC], lg[EE];
    int tid = threadIdx.x, w = tid >> 5, ln = tid & 31;
    int nf = g_nfix; if (nf > FIXCAP) nf = FIXCAP;
    for (int fi = blockIdx.x; fi < nf; fi += gridDim.x) {
        int t = g_fix[fi];
        __syncthreads();
        xr[tid] = x[(size_t)t * CC + tid];
        xr[tid + 256] = x[(size_t)t * CC + tid + 256];
        __syncthreads();
        for (int c = w; c < CC; c += 8) {
            const float* wr = wg1 + (size_t)c * CC;
            float a = 0.f;
#pragma unroll
            for (int j = 0; j < 16; j++) { int k = j * 32 + ln; a += xr[k] * wr[k]; }
#pragma unroll
            for (int off = 16; off; off >>= 1) a += __shfl_xor_sync(0xffffffffu, a, off);
            if (ln == 0) {
                float mu = g_sum[c] * (1.0f / TT);
                float var = g_sumsq[c] * (1.0f / TT) - mu * mu;
                rr[c] = fmaxf(gamma[c] * (a - mu) * rsqrtf(var + 1e-5f) + beta[c], 0.f);
            }
        }
        __syncthreads();
        if (w < EE) {
            const float* we = wg2 + w * CC;
            float a = 0.f;
#pragma unroll
            for (int j = 0; j < 16; j++) { int k = j * 32 + ln; a += rr[k] * we[k]; }
#pragma unroll
            for (int off = 16; off; off >>= 1) a += __shfl_xor_sync(0xffffffffu, a, off);
            if (ln == 0) lg[w] = a + bg2[w];
        }
        __syncthreads();
        if (tid == 0) {
            int e0 = 0; float v0 = lg[0];
#pragma unroll
            for (int e = 1; e < EE; e++) if (lg[e] > v0) { v0 = lg[e]; e0 = e; }
            int e1 = -1; float v1 = -1e30f;
#pragma unroll
            for (int e = 0; e < EE; e++) if (e != e0 && lg[e] > v1) { v1 = lg[e]; e1 = e; }
            float ex = expf(v1 - v0);
            float inv = 1.f / (1.f + ex);
            g_re[t * 2] = e0; g_re[t * 2 + 1] = e1;
            g_rw[t * 2] = inv; g_rw[t * 2 + 1] = ex * inv;
            atomicAdd(&g_usage[e0], inv);
            atomicAdd(&g_usage[e1], ex * inv);
        }
    }
}

// ---------------- scale h1 by routing weights, split to bf16 hi/lo ------------
__global__ __launch_bounds__(256) void k_scale() {
    int idx4 = blockIdx.x * 256 + threadIdx.x;
    int t = idx4 >> 5;
    int k4 = (idx4 & 31) << 2;
    int e = k4 >> 4;
    int e0 = __ldg(&g_re[t * 2]), e1 = __ldg(&g_re[t * 2 + 1]);
    float w = (e == e0) ? __ldg(&g_rw[t * 2]) : ((e == e1) ? __ldg(&g_rw[t * 2 + 1]) : 0.f);
    float4 v = *(const float4*)(g_h1 + (size_t)t * 128 + k4);
    float a[4] = {w * v.x, w * v.y, w * v.z, w * v.w};
    unsigned hh[4], ll[4];
#pragma unroll
    for (int i = 0; i < 4; i++) {
        __nv_bfloat16 hb = __float2bfloat16(a[i]);
        __nv_bfloat16 lb = __float2bfloat16(a[i] - __bfloat162float(hb));
        hh[i] = ((__nv_bfloat16_raw)hb).x;
        ll[i] = ((__nv_bfloat16_raw)lb).x;
    }
    uint2 ph = {hh[0] | (hh[1] << 16), hh[2] | (hh[3] << 16)};
    uint2 pl = {ll[0] | (ll[1] << 16), ll[2] | (ll[3] << 16)};
    ((uint2*)g_ah)[idx4] = ph;
    ((uint2*)g_al)[idx4] = pl;
}

// ---------------- expert GEMM2 + weighted bias + transpose -------------------
// A (ah|al) double-buffered 2x32KB; B (w2h|w2l) single 32KB (L2-hot). 96KB -> occ 2.
#define ESMEM2 98304

__global__ __launch_bounds__(256, 2) void k_egemm2(const float* __restrict__ b2,
                                                   float* __restrict__ out) {
    extern __shared__ char smc[];
    uint32_t sb = smem_u32(smc);
    int tid = threadIdx.x;
    int n0 = blockIdx.x * 128, m0 = blockIdx.y * 128;
    int warp = tid >> 5, lane = tid & 31;
    int wm = warp >> 1, wn = warp & 1;

    const __nv_bfloat16* ah = g_ah + (size_t)m0 * 128;
    const __nv_bfloat16* al = g_al + (size_t)m0 * 128;
    const __nv_bfloat16* bh = g_w2h + (size_t)n0 * 128;
    const __nv_bfloat16* bl = g_w2l + (size_t)n0 * 128;

    float acc[2][8][4];
#pragma unroll
    for (int i = 0; i < 2; i++)
#pragma unroll
        for (int j = 0; j < 8; j++)
#pragma unroll
            for (int q = 0; q < 4; q++) acc[i][j][q] = 0.f;

    int li = lane & 7, lm = lane >> 3;
    int a_row = (lm & 1) * 8 + li, a_cb = (lm >> 1) * 16;
    int b_row = (lm >> 1) * 8 + li, b_cb = (lm & 1) * 16;

#define LOADA2(S, K0) do {                                                      \
        uint32_t sbs = sb + (S) * 32768;                                        \
        const __nv_bfloat16* srcs[2] = {ah, al};                                \
        _Pragma("unroll")                                                       \
        for (int tt = 0; tt < 2; tt++) {                                        \
            const __nv_bfloat16* src = srcs[tt];                                \
            _Pragma("unroll")                                                   \
            for (int it = 0; it < 4; it++) {                                    \
                int idx = tid + it * 256;                                       \
                int r = idx >> 3, c16 = idx & 7;                                \
                const void* g = src + (size_t)r * 128 + (K0) + c16 * 8;         \
                uint32_t bo = (uint32_t)((r << 7) | (c16 << 4));                \
                bo ^= (bo >> 3) & 0x70;                                         \
                CP16(sbs + tt * 16384 + bo, g);                                 \
            }                                                                   \
        }                                                                       \
    } while (0)
#define LOADB2(K0) do {                                                         \
        uint32_t sbs = sb + 65536;                                              \
        const __nv_bfloat16* srcs[2] = {bh, bl};                                \
        _Pragma("unroll")                                                       \
        for (int tt = 0; tt < 2; tt++) {                                        \
            const __nv_bfloat16* src = srcs[tt];                                \
            _Pragma("unroll")                                                   \
            for (int it = 0; it < 4; it++) {                                    \
                int idx = tid + it * 256;                                       \
                int r = idx >> 3, c16 = idx & 7;                                \
                const void* g = src + (size_t)r * 128 + (K0) + c16 * 8;         \
                uint32_t bo = (uint32_t)((r << 7) | (c16 << 4));                \
                bo ^= (bo >> 3) & 0x70;                                         \
                CP16(sbs + tt * 16384 + bo, g);                                 \
            }                                                                   \
        }                                                                       \
    } while (0)

    LOADB2(0);
    LOADA2(0, 0);
    CPCOMMIT();                 // G0
    LOADA2(1, 64);
    CPCOMMIT();                 // G1

    const int aoff[3] = {0, 0, 16384};
    const int boff[3] = {0, 16384, 0};

    for (int kc = 0; kc < 2; kc++) {
        int s = kc & 1;
        if (kc > 0) {
            __syncthreads();
            LOADB2(64);
            CPCOMMIT();
            CPWAIT(0);
        } else {
            CPWAIT(1);
        }
        __syncthreads();

#pragma unroll
        for (int tp = 0; tp < 3; tp++) {
            uint32_t abase = sb + s * 32768 + aoff[tp];
            uint32_t bbase = sb + 65536 + boff[tp];
#pragma unroll
            for (int ks = 0; ks < 4; ks++) {
                int kb = ks * 32;
                uint32_t af[2][4];
#pragma unroll
                for (int mi = 0; mi < 2; mi++) {
                    int r = wm * 32 + mi * 16 + a_row;
                    uint32_t cb = (uint32_t)(kb + a_cb);
                    ldm4(af[mi], abase + (r << 7) + (cb ^ ((r & 7) << 4)));
                }
                uint32_t bfr[4][4];
#pragma unroll
                for (int p = 0; p < 4; p++) {
                    int r = wn * 64 + p * 16 + b_row;
                    uint32_t cb = (uint32_t)(kb + b_cb);
                    ldm4(bfr[p], bbase + (r << 7) + (cb ^ ((r & 7) << 4)));
                }
#pragma unroll
                for (int mi = 0; mi < 2; mi++)
#pragma unroll
                    for (int ni = 0; ni < 8; ni++)
                        mma16816(acc[mi][ni], af[mi],
                                 bfr[ni >> 1][(ni & 1) * 2],
                                 bfr[ni >> 1][(ni & 1) * 2 + 1]);
            }
        }
    }
#undef LOADA2
#undef LOADB2
    __syncthreads();

    // epilogue: stage to smem, add weighted bias, transposed store
    float* ot  = (float*)smc;            // 128 x 129
    float* b2s = ot + 128 * 129;         // 8 x 128
    float* srw = b2s + 1024;             // 256
    int*   sre = (int*)(srw + 256);      // 256

    int g = lane >> 2, tg = lane & 3;
#pragma unroll
    for (int mi = 0; mi < 2; mi++) {
        int rl = wm * 32 + mi * 16 + g;
#pragma unroll
        for (int ni = 0; ni < 8; ni++) {
            int cl = wn * 64 + ni * 8 + tg * 2;
            ot[rl * 129 + cl] = acc[mi][ni][0];
            ot[rl * 129 + cl + 1] = acc[mi][ni][1];
            ot[(rl + 8) * 129 + cl] = acc[mi][ni][2];
            ot[(rl + 8) * 129 + cl + 1] = acc[mi][ni][3];
        }
    }
    if (tid < 256) {
        sre[tid] = g_re[m0 * 2 + tid];
        srw[tid] = g_rw[m0 * 2 + tid];
    }
    for (int i = tid; i < 1024; i += 256) {
        int e = i >> 7, cl = i & 127;
        b2s[i] = b2[e * CC + n0 + cl];
    }
    __syncthreads();

    int c = tid >> 1, half = tid & 1;
    int batch = m0 >> 12, nb = m0 & (NNN - 1);
    float* ob = out + (size_t)batch * CC * NNN + (size_t)(n0 + c) * NNN + nb + half * 64;
#pragma unroll 2
    for (int tt4 = 0; tt4 < 64; tt4 += 4) {
        float4 v;
        float vv[4];
#pragma unroll
        for (int q = 0; q < 4; q++) {
            int ti = half * 64 + tt4 + q;
            float val = ot[ti * 129 + c];
            int ee0 = sre[2 * ti], ee1 = sre[2 * ti + 1];
            val += srw[2 * ti] * b2s[ee0 * 128 + c] + srw[2 * ti + 1] * b2s[ee1 * 128 + c];
            vv[q] = val;
        }
        v.x = vv[0]; v.y = vv[1]; v.z = vv[2]; v.w = vv[3];
        *(float4*)(ob + tt4) = v;
    }
}

// ---------------- load-balance loss -------------------------------------------
__global__ void k_lb(float* __restrict__ out, long long out_size) {
    if (threadIdx.x == 0 && out_size > (long long)BB * CC * NNN) {
        float s = 0.f;
#pragma unroll
        for (int e = 0; e < EE; e++) {
            float u = g_usage[e] * (1.0f / TT);
            s += u * u;
        }
        out[(size_t)BB * CC * NNN] = s * (float)EE;
    }
}

// ---------------- launch --------------------------------------------------------
extern "C" void kernel_launch(void* const* d_in, const int* in_sizes, int n_in,
                              void* d_out, int out_size) {
    const float* x     = (const float*)d_in[0];
    const float* wg1   = (const float*)d_in[1];
    const float* bg1   = (const float*)d_in[2];
    const float* gamma = (const float*)d_in[3];
    const float* beta  = (const float*)d_in[4];
    const float* wg2   = (const float*)d_in[5];
    const float* bg2   = (const float*)d_in[6];
    const float* w1    = (const float*)d_in[7];
    const float* b1    = (const float*)d_in[8];
    const float* w2    = (const float*)d_in[9];
    const float* b2    = (const float*)d_in[10];
    float* out = (float*)d_out;

    cudaFuncSetAttribute(k_gemm,   cudaFuncAttributeMaxDynamicSharedMemorySize, GSMEM);
    cudaFuncSetAttribute(k_egemm1, cudaFuncAttributeMaxDynamicSharedMemorySize, ESMEM1);
    cudaFuncSetAttribute(k_egemm2, cudaFuncAttributeMaxDynamicSharedMemorySize, ESMEM2);

    k_zero<<<1, 512>>>();
    {
        long long tot4 = ((long long)TT * CC + (long long)CC * CC) / 4;
        int nb = (int)((tot4 + 255) / 256);
        k_split<<<nb, 256>>>(x, wg1);
    }
    k_split2<<<512, 256>>>(w1, w2);
    dim3 gg(CC / 128, TT / 128);
    k_gemm<<<gg, 256, GSMEM>>>(bg1);
    k_egemm1<<<TT / 128, 256, ESMEM1>>>(b1);
    k_route<<<TT / 32, 256>>>(gamma, beta, wg2, bg2);
    k_fix<<<256, 256>>>(x, wg1, gamma, beta, wg2, bg2);
    k_scale<<<TT * 128 / 4 / 256, 256>>>();
    dim3 g2(CC / 128, TT / 128);
    k_egemm2<<<g2, 256, ESMEM2>>>(b2, out);
    k_lb<<<1, 32>>>(out, (long long)out_size);
}

// round 11
// speedup vs baseline: 1.1657x; 1.1657x over previous
#include <cuda_runtime.h>
#include <cuda_bf16.h>
#include <math.h>
#include <stdint.h>

#define TT   32768
#define CC   512
#define EE   8
#define HH   16
#define BB   8
#define NNN  4096
#define FIXCAP 8192

// ---------------- scratch (static device globals; no allocation) -------------
__device__ float g_h[(size_t)TT * CC];     // gate hidden, 64MB
__device__ float g_h1[(size_t)TT * 128];   // expert hidden (all experts), 16MB
__device__ int   g_re[TT * 2];
__device__ float g_rw[TT * 2];
__device__ float g_sum[CC];
__device__ float g_sumsq[CC];
__device__ float g_usage[EE];
__device__ int   g_nfix;
__device__ int   g_fix[FIXCAP];
__device__ __align__(16) __nv_bfloat16 g_xh[(size_t)TT * CC];
__device__ __align__(16) __nv_bfloat16 g_xl[(size_t)TT * CC];
__device__ __align__(16) __nv_bfloat16 g_wh[CC * CC];
__device__ __align__(16) __nv_bfloat16 g_wl[CC * CC];
__device__ __align__(16) __nv_bfloat16 g_w1h[128 * CC];   // W1cat^T [n=e*16+h][k=c]
__device__ __align__(16) __nv_bfloat16 g_w1l[128 * CC];
__device__ __align__(16) __nv_bfloat16 g_w2h[CC * 128];   // W2cat^T [n=c][k=e*16+h]
__device__ __align__(16) __nv_bfloat16 g_w2l[CC * 128];
__device__ __align__(16) __nv_bfloat16 g_ah[(size_t)TT * 128];  // h1scaled hi
__device__ __align__(16) __nv_bfloat16 g_al[(size_t)TT * 128];  // h1scaled lo

// ---------------- PTX helpers -------------------------------------------------
__device__ __forceinline__ uint32_t smem_u32(const void* p) {
    uint32_t a;
    asm("{ .reg .u64 t; cvta.to.shared.u64 t, %1; cvt.u32.u64 %0, t; }" : "=r"(a) : "l"(p));
    return a;
}
__device__ __forceinline__ void ldm4(uint32_t* r, uint32_t a) {
    asm volatile("ldmatrix.sync.aligned.m8n8.x4.shared.b16 {%0,%1,%2,%3}, [%4];"
                 : "=r"(r[0]), "=r"(r[1]), "=r"(r[2]), "=r"(r[3]) : "r"(a));
}
__device__ __forceinline__ void mma16816(float* d, const uint32_t* a,
                                         uint32_t b0, uint32_t b1) {
    asm volatile(
        "mma.sync.aligned.m16n8k16.row.col.f32.bf16.bf16.f32 "
        "{%0,%1,%2,%3}, {%4,%5,%6,%7}, {%8,%9}, {%0,%1,%2,%3};"
        : "+f"(d[0]), "+f"(d[1]), "+f"(d[2]), "+f"(d[3])
        : "r"(a[0]), "r"(a[1]), "r"(a[2]), "r"(a[3]), "r"(b0), "r"(b1));
}
#define CP16(dst, src) asm volatile("cp.async.cg.shared.global [%0], [%1], 16;" ::"r"(dst), "l"(src) : "memory")
#define CPCOMMIT()     asm volatile("cp.async.commit_group;" ::: "memory")
#define CPWAIT(n)      asm volatile("cp.async.wait_group %0;" ::"n"(n) : "memory")

// ---------------- zero accumulators ------------------------------------------
__global__ void k_zero() {
    int i = threadIdx.x;
    if (i < CC) { g_sum[i] = 0.f; g_sumsq[i] = 0.f; }
    if (i < EE) g_usage[i] = 0.f;
    if (i == 0) g_nfix = 0;
}

// ---------------- bf16 splits --------------------------------------------------
__global__ __launch_bounds__(256) void k_split(const float* __restrict__ x,
                                               const float* __restrict__ wg1) {
    size_t i4 = (size_t)blockIdx.x * 256 + threadIdx.x;
    const size_t nx = (size_t)TT * CC / 4, nw = (size_t)CC * CC / 4;
    const float* s; __nv_bfloat16 *dh, *dl; size_t o;
    if (i4 < nx)           { s = x;   o = i4;      dh = g_xh; dl = g_xl; }
    else if (i4 < nx + nw) { s = wg1; o = i4 - nx; dh = g_wh; dl = g_wl; }
    else return;
    float4 v = ((const float4*)s)[o];
    float a[4] = {v.x, v.y, v.z, v.w};
    unsigned hh[4], ll[4];
#pragma unroll
    for (int i = 0; i < 4; i++) {
        __nv_bfloat16 hb = __float2bfloat16(a[i]);
        __nv_bfloat16 lb = __float2bfloat16(a[i] - __bfloat162float(hb));
        hh[i] = ((__nv_bfloat16_raw)hb).x;
        ll[i] = ((__nv_bfloat16_raw)lb).x;
    }
    uint2 ph = {hh[0] | (hh[1] << 16), hh[2] | (hh[3] << 16)};
    uint2 pl = {ll[0] | (ll[1] << 16), ll[2] | (ll[3] << 16)};
    ((uint2*)dh)[o] = ph;
    ((uint2*)dl)[o] = pl;
}

// expert weight repack + split
__global__ __launch_bounds__(256) void k_split2(const float* __restrict__ w1,
                                                const float* __restrict__ w2) {
    int idx = blockIdx.x * 256 + threadIdx.x;
    if (idx < 65536) {
        int e = idx >> 13, r = idx & 8191, c = r >> 4, h = r & 15;
        float v = w1[idx];
        __nv_bfloat16 hb = __float2bfloat16(v);
        __nv_bfloat16 lb = __float2bfloat16(v - __bfloat162float(hb));
        int n = e * 16 + h;
        g_w1h[n * CC + c] = hb;
        g_w1l[n * CC + c] = lb;
    } else if (idx < 131072) {
        int j = idx - 65536;
        int e = j >> 13, r = j & 8191, h = r >> 9, c = r & 511;
        float v = w2[j];
        __nv_bfloat16 hb = __float2bfloat16(v);
        __nv_bfloat16 lb = __float2bfloat16(v - __bfloat162float(hb));
        int n = e * 16 + h;
        g_w2h[c * 128 + n] = hb;
        g_w2l[c * 128 + n] = lb;
    }
}

// ---------------- gate GEMM1 (HMMA, 2-term, cp.async 2-stage) -----------------
// A fragments hoisted across the two term pairs; B frags reuse one register set.
#define STG 49152
#define GSMEM (2 * STG)

__global__ __launch_bounds__(256, 2) void k_gemm(const float* __restrict__ bg1) {
    extern __shared__ char smc[];
    uint32_t sb = smem_u32(smc);
    int tid = threadIdx.x;
    int n0 = blockIdx.x * 128, m0 = blockIdx.y * 128;
    int warp = tid >> 5, lane = tid & 31;
    int wm = warp >> 1, wn = warp & 1;

    const __nv_bfloat16* xs  = g_xh + (size_t)m0 * CC;
    const __nv_bfloat16* whs = g_wh + (size_t)n0 * CC;
    const __nv_bfloat16* wls = g_wl + (size_t)n0 * CC;

    float acc[2][8][4];
#pragma unroll
    for (int i = 0; i < 2; i++)
#pragma unroll
        for (int j = 0; j < 8; j++)
#pragma unroll
            for (int q = 0; q < 4; q++) acc[i][j][q] = 0.f;

    int li = lane & 7, lm = lane >> 3;
    int a_row = (lm & 1) * 8 + li, a_cb = (lm >> 1) * 16;
    int b_row = (lm >> 1) * 8 + li, b_cb = (lm & 1) * 16;

#define LOADSTAGE(S, K0) do {                                                   \
        uint32_t sbs = sb + (S) * STG;                                          \
        const __nv_bfloat16* srcs[3] = {xs, whs, wls};                          \
        _Pragma("unroll")                                                       \
        for (int tt = 0; tt < 3; tt++) {                                        \
            const __nv_bfloat16* src = srcs[tt];                                \
            _Pragma("unroll")                                                   \
            for (int it = 0; it < 4; it++) {                                    \
                int idx = tid + it * 256;                                       \
                int r = idx >> 3, c16 = idx & 7;                                \
                const void* g = src + (size_t)r * CC + (K0) + c16 * 8;          \
                uint32_t bo = (uint32_t)((r << 7) | (c16 << 4));                \
                bo ^= (bo >> 3) & 0x70;                                         \
                CP16(sbs + tt * 16384 + bo, g);                                 \
            }                                                                   \
        }                                                                       \
    } while (0)

    LOADSTAGE(0, 0);
    CPCOMMIT();

    for (int kc = 0; kc < 8; kc++) {
        int s = kc & 1;
        if (kc < 7) {
            LOADSTAGE(s ^ 1, (kc + 1) * 64);
            CPCOMMIT();
            CPWAIT(1);
        } else {
            CPWAIT(0);
        }
        __syncthreads();

        uint32_t abase = sb + s * STG;
#pragma unroll
        for (int ks = 0; ks < 4; ks++) {
            int kb = ks * 32;
            uint32_t af[2][4];
#pragma unroll
            for (int mi = 0; mi < 2; mi++) {
                int r = wm * 32 + mi * 16 + a_row;
                uint32_t cb = (uint32_t)(kb + a_cb);
                ldm4(af[mi], abase + (r << 7) + (cb ^ ((r & 7) << 4)));
            }
            uint32_t bfr[4][4];
#pragma unroll
            for (int tp = 0; tp < 2; tp++) {
                uint32_t bbase = abase + 16384 + tp * 16384;
#pragma unroll
                for (int p = 0; p < 4; p++) {
                    int r = wn * 64 + p * 16 + b_row;
                    uint32_t cb = (uint32_t)(kb + b_cb);
                    ldm4(bfr[p], bbase + (r << 7) + (cb ^ ((r & 7) << 4)));
                }
#pragma unroll
                for (int mi = 0; mi < 2; mi++)
#pragma unroll
                    for (int ni = 0; ni < 8; ni++)
                        mma16816(acc[mi][ni], af[mi],
                                 bfr[ni >> 1][(ni & 1) * 2],
                                 bfr[ni >> 1][(ni & 1) * 2 + 1]);
            }
        }
        __syncthreads();
    }
#undef LOADSTAGE

    int g = lane >> 2, tg = lane & 3;
#pragma unroll
    for (int mi = 0; mi < 2; mi++) {
        int row = m0 + wm * 32 + mi * 16 + g;
#pragma unroll
        for (int ni = 0; ni < 8; ni++) {
            int col = n0 + wn * 64 + ni * 8 + tg * 2;
            float bx = bg1[col], by = bg1[col + 1];
            acc[mi][ni][0] += bx; acc[mi][ni][1] += by;
            acc[mi][ni][2] += bx; acc[mi][ni][3] += by;
            float2 v0 = {acc[mi][ni][0], acc[mi][ni][1]};
            float2 v1 = {acc[mi][ni][2], acc[mi][ni][3]};
            *(float2*)(g_h + (size_t)row * CC + col) = v0;
            *(float2*)(g_h + (size_t)(row + 8) * CC + col) = v1;
        }
    }

    float* ssum = (float*)smc;
    float* ssq  = (float*)(smc + 512);
    if (tid < 128) { ssum[tid] = 0.f; ssq[tid] = 0.f; }
    __syncthreads();
#pragma unroll
    for (int ni = 0; ni < 8; ni++) {
        int colr = wn * 64 + ni * 8 + tg * 2;
        float s0 = 0.f, s1 = 0.f, q0 = 0.f, q1 = 0.f;
#pragma unroll
        for (int mi = 0; mi < 2; mi++) {
            float a0 = acc[mi][ni][0], a1 = acc[mi][ni][1];
            float a2 = acc[mi][ni][2], a3 = acc[mi][ni][3];
            s0 += a0 + a2; s1 += a1 + a3;
            q0 += a0 * a0 + a2 * a2; q1 += a1 * a1 + a3 * a3;
        }
#pragma unroll
        for (int off = 4; off < 32; off <<= 1) {
            s0 += __shfl_xor_sync(0xffffffffu, s0, off);
            s1 += __shfl_xor_sync(0xffffffffu, s1, off);
            q0 += __shfl_xor_sync(0xffffffffu, q0, off);
            q1 += __shfl_xor_sync(0xffffffffu, q1, off);
        }
        if (g == 0) {
            atomicAdd(&ssum[colr], s0); atomicAdd(&ssum[colr + 1], s1);
            atomicAdd(&ssq[colr], q0);  atomicAdd(&ssq[colr + 1], q1);
        }
    }
    __syncthreads();
    if (tid < 128) {
        atomicAdd(&g_sum[n0 + tid], ssum[tid]);
        atomicAdd(&g_sumsq[n0 + tid], ssq[tid]);
    }
}

// ---------------- expert GEMM1: h1all = relu(x @ W1cat + b1) (3-term) --------
// R9 structure (2x64KB stages, occ 1). A (Ah,Al) loaded once per ks;
// Bh reused for both AhBh and AlBh; Bl reuses the same registers.
#define ESMEM 131072

__global__ __launch_bounds__(256, 1) void k_egemm1(const float* __restrict__ b1) {
    extern __shared__ char smc[];
    uint32_t sb = smem_u32(smc);
    int tid = threadIdx.x;
    int m0 = blockIdx.x * 128;
    int warp = tid >> 5, lane = tid & 31;
    int wm = warp >> 1, wn = warp & 1;

    const __nv_bfloat16* ah = g_xh + (size_t)m0 * CC;
    const __nv_bfloat16* al = g_xl + (size_t)m0 * CC;

    float acc[2][8][4];
#pragma unroll
    for (int i = 0; i < 2; i++)
#pragma unroll
        for (int j = 0; j < 8; j++)
#pragma unroll
            for (int q = 0; q < 4; q++) acc[i][j][q] = 0.f;

    int li = lane & 7, lm = lane >> 3;
    int a_row = (lm & 1) * 8 + li, a_cb = (lm >> 1) * 16;
    int b_row = (lm >> 1) * 8 + li, b_cb = (lm & 1) * 16;

#define LOADS1(S, K0) do {                                                      \
        uint32_t sbs = sb + (S) * 65536;                                        \
        const __nv_bfloat16* srcs[4] = {ah, al, g_w1h, g_w1l};                  \
        _Pragma("unroll")                                                       \
        for (int tt = 0; tt < 4; tt++) {                                        \
            const __nv_bfloat16* src = srcs[tt];                                \
            _Pragma("unroll")                                                   \
            for (int it = 0; it < 4; it++) {                                    \
                int idx = tid + it * 256;                                       \
                int r = idx >> 3, c16 = idx & 7;                                \
                const void* g = src + (size_t)r * CC + (K0) + c16 * 8;          \
                uint32_t bo = (uint32_t)((r << 7) | (c16 << 4));                \
                bo ^= (bo >> 3) & 0x70;                                         \
                CP16(sbs + tt * 16384 + bo, g);                                 \
            }                                                                   \
        }                                                                       \
    } while (0)

    LOADS1(0, 0);
    CPCOMMIT();

    for (int kc = 0; kc < 8; kc++) {
        int s = kc & 1;
        if (kc < 7) {
            LOADS1(s ^ 1, (kc + 1) * 64);
            CPCOMMIT();
            CPWAIT(1);
        } else {
            CPWAIT(0);
        }
        __syncthreads();

        uint32_t stg = sb + s * 65536;
#pragma unroll
        for (int ks = 0; ks < 4; ks++) {
            int kb = ks * 32;
            uint32_t afh[2][4], afl[2][4];
#pragma unroll
            for (int mi = 0; mi < 2; mi++) {
                int r = wm * 32 + mi * 16 + a_row;
                uint32_t cb = (uint32_t)(kb + a_cb);
                uint32_t off = (r << 7) + (cb ^ ((r & 7) << 4));
                ldm4(afh[mi], stg + off);
                ldm4(afl[mi], stg + 16384 + off);
            }
            uint32_t bfr[4][4];
            // Bh: used by AhBh and AlBh
#pragma unroll
            for (int p = 0; p < 4; p++) {
                int r = wn * 64 + p * 16 + b_row;
                uint32_t cb = (uint32_t)(kb + b_cb);
                ldm4(bfr[p], stg + 32768 + (r << 7) + (cb ^ ((r & 7) << 4)));
            }
#pragma unroll
            for (int mi = 0; mi < 2; mi++)
#pragma unroll
                for (int ni = 0; ni < 8; ni++) {
                    mma16816(acc[mi][ni], afh[mi],
                             bfr[ni >> 1][(ni & 1) * 2], bfr[ni >> 1][(ni & 1) * 2 + 1]);
                    mma16816(acc[mi][ni], afl[mi],
                             bfr[ni >> 1][(ni & 1) * 2], bfr[ni >> 1][(ni & 1) * 2 + 1]);
                }
            // Bl: AhBl
#pragma unroll
            for (int p = 0; p < 4; p++) {
                int r = wn * 64 + p * 16 + b_row;
                uint32_t cb = (uint32_t)(kb + b_cb);
                ldm4(bfr[p], stg + 49152 + (r << 7) + (cb ^ ((r & 7) << 4)));
            }
#pragma unroll
            for (int mi = 0; mi < 2; mi++)
#pragma unroll
                for (int ni = 0; ni < 8; ni++)
                    mma16816(acc[mi][ni], afh[mi],
                             bfr[ni >> 1][(ni & 1) * 2], bfr[ni >> 1][(ni & 1) * 2 + 1]);
        }
        __syncthreads();
    }
#undef LOADS1

    int g = lane >> 2, tg = lane & 3;
#pragma unroll
    for (int mi = 0; mi < 2; mi++) {
        int row = m0 + wm * 32 + mi * 16 + g;
#pragma unroll
        for (int ni = 0; ni < 8; ni++) {
            int col = wn * 64 + ni * 8 + tg * 2;
            float bx = b1[col], by = b1[col + 1];
            float2 v0 = {fmaxf(acc[mi][ni][0] + bx, 0.f), fmaxf(acc[mi][ni][1] + by, 0.f)};
            float2 v1 = {fmaxf(acc[mi][ni][2] + bx, 0.f), fmaxf(acc[mi][ni][3] + by, 0.f)};
            *(float2*)(g_h1 + (size_t)row * 128 + col) = v0;
            *(float2*)(g_h1 + (size_t)(row + 8) * 128 + col) = v1;
        }
    }
}

// ---------------- routing: stream h from gmem, warp-per-token ----------------
#define RSTR 516
__global__ __launch_bounds__(256) void k_route(const float* __restrict__ gamma,
                                               const float* __restrict__ beta,
                                               const float* __restrict__ wg2,
                                               const float* __restrict__ bg2) {
    __shared__ float ws[EE * RSTR];
    __shared__ float sc[CC], sh[CC];
    __shared__ float susage[EE];
    __shared__ float sbg2[EE];
    int tid = threadIdx.x, warp = tid >> 5, lane = tid & 31;

    if (tid < EE) { susage[tid] = 0.f; sbg2[tid] = bg2[tid]; }
    for (int c = tid; c < CC; c += 256) {
        float m = g_sum[c] * (1.0f / TT);
        float v = g_sumsq[c] * (1.0f / TT) - m * m;
        float rs = rsqrtf(v + 1e-5f);
        float s = gamma[c] * rs;
        sc[c] = s;
        sh[c] = beta[c] - m * s;
    }
    for (int i4 = tid; i4 < EE * 128; i4 += 256) {
        int e = i4 >> 7, c4 = (i4 & 127) << 2;
        float4 v = *(const float4*)(wg2 + e * CC + c4);
        *(float4*)(ws + e * RSTR + c4) = v;
    }
    __syncthreads();

#pragma unroll 1
    for (int j = 0; j < 4; j++) {
        int t = blockIdx.x * 32 + warp * 4 + j;
        float p[EE];
#pragma unroll
        for (int e = 0; e < EE; e++) p[e] = 0.f;
#pragma unroll 1
        for (int i = 0; i < 4; i++) {
            int c4 = i * 128 + lane * 4;
            float4 v = *(const float4*)(g_h + (size_t)t * CC + c4);
            float4 r;
            r.x = fmaxf(sc[c4 + 0] * v.x + sh[c4 + 0], 0.f);
            r.y = fmaxf(sc[c4 + 1] * v.y + sh[c4 + 1], 0.f);
            r.z = fmaxf(sc[c4 + 2] * v.z + sh[c4 + 2], 0.f);
            r.w = fmaxf(sc[c4 + 3] * v.w + sh[c4 + 3], 0.f);
#pragma unroll
            for (int e = 0; e < EE; e++) {
                float4 w = *(const float4*)(ws + e * RSTR + c4);
                p[e] += r.x * w.x + r.y * w.y + r.z * w.z + r.w * w.w;
            }
        }
#pragma unroll
        for (int e = 0; e < EE; e++)
#pragma unroll
            for (int off = 16; off; off >>= 1)
                p[e] += __shfl_xor_sync(0xffffffffu, p[e], off);

        if (lane == 0) {
            float l[EE];
#pragma unroll
            for (int e = 0; e < EE; e++) l[e] = p[e] + sbg2[e];
            int e0 = 0; float v0 = l[0];
#pragma unroll
            for (int e = 1; e < EE; e++) if (l[e] > v0) { v0 = l[e]; e0 = e; }
            int e1 = -1; float v1 = -1e30f;
#pragma unroll
            for (int e = 0; e < EE; e++) if (e != e0 && l[e] > v1) { v1 = l[e]; e1 = e; }
            float v2 = -1e30f;
#pragma unroll
            for (int e = 0; e < EE; e++) if (e != e0 && e != e1 && l[e] > v2) v2 = l[e];
            float ex = expf(v1 - v0);
            float inv = 1.f / (1.f + ex);
            g_re[t * 2] = e0; g_re[t * 2 + 1] = e1;
            g_rw[t * 2] = inv; g_rw[t * 2 + 1] = ex * inv;
            bool flagged = (v1 - v2) < 2.5e-3f;
            if (flagged) {
                int pos = atomicAdd(&g_nfix, 1);
                if (pos < FIXCAP) g_fix[pos] = t; else flagged = false;
            }
            if (!flagged) {
                atomicAdd(&susage[e0], inv);
                atomicAdd(&susage[e1], ex * inv);
            }
        }
    }
    __syncthreads();
    if (tid < EE) atomicAdd(&g_usage[tid], susage[tid]);
}

// ---------------- exact fp32 recompute for near-tie tokens -------------------
__global__ __launch_bounds__(256) void k_fix(const float* __restrict__ x,
                                             const float* __restrict__ wg1,
                                             const float* __restrict__ gamma,
                                             const float* __restrict__ beta,
                                             const float* __restrict__ wg2,
                                             const float* __restrict__ bg2) {
    __shared__ float xr[CC], rr[CC], lg[EE];
    int tid = threadIdx.x, w = tid >> 5, ln = tid & 31;
    int nf = g_nfix; if (nf > FIXCAP) nf = FIXCAP;
    for (int fi = blockIdx.x; fi < nf; fi += gridDim.x) {
        int t = g_fix[fi];
        __syncthreads();
        xr[tid] = x[(size_t)t * CC + tid];
        xr[tid + 256] = x[(size_t)t * CC + tid + 256];
        __syncthreads();
        for (int c = w; c < CC; c += 8) {
            const float* wr = wg1 + (size_t)c * CC;
            float a = 0.f;
#pragma unroll
            for (int j = 0; j < 16; j++) { int k = j * 32 + ln; a += xr[k] * wr[k]; }
#pragma unroll
            for (int off = 16; off; off >>= 1) a += __shfl_xor_sync(0xffffffffu, a, off);
            if (ln == 0) {
                float mu = g_sum[c] * (1.0f / TT);
                float var = g_sumsq[c] * (1.0f / TT) - mu * mu;
                rr[c] = fmaxf(gamma[c] * (a - mu) * rsqrtf(var + 1e-5f) + beta[c], 0.f);
            }
        }
        __syncthreads();
        if (w < EE) {
            const float* we = wg2 + w * CC;
            float a = 0.f;
#pragma unroll
            for (int j = 0; j < 16; j++) { int k = j * 32 + ln; a += rr[k] * we[k]; }
#pragma unroll
            for (int off = 16; off; off >>= 1) a += __shfl_xor_sync(0xffffffffu, a, off);
            if (ln == 0) lg[w] = a + bg2[w];
        }
        __syncthreads();
        if (tid == 0) {
            int e0 = 0; float v0 = lg[0];
#pragma unroll
            for (int e = 1; e < EE; e++) if (lg[e] > v0) { v0 = lg[e]; e0 = e; }
            int e1 = -1; float v1 = -1e30f;
#pragma unroll
            for (int e = 0; e < EE; e++) if (e != e0 && lg[e] > v1) { v1 = lg[e]; e1 = e; }
            float ex = expf(v1 - v0);
            float inv = 1.f / (1.f + ex);
            g_re[t * 2] = e0; g_re[t * 2 + 1] = e1;
            g_rw[t * 2] = inv; g_rw[t * 2 + 1] = ex * inv;
            atomicAdd(&g_usage[e0], inv);
            atomicAdd(&g_usage[e1], ex * inv);
        }
    }
}

// ---------------- scale h1 by routing weights, split to bf16 hi/lo ------------
__global__ __launch_bounds__(256) void k_scale() {
    int idx4 = blockIdx.x * 256 + threadIdx.x;
    int t = idx4 >> 5;
    int k4 = (idx4 & 31) << 2;
    int e = k4 >> 4;
    int e0 = __ldg(&g_re[t * 2]), e1 = __ldg(&g_re[t * 2 + 1]);
    float w = (e == e0) ? __ldg(&g_rw[t * 2]) : ((e == e1) ? __ldg(&g_rw[t * 2 + 1]) : 0.f);
    float4 v = *(const float4*)(g_h1 + (size_t)t * 128 + k4);
    float a[4] = {w * v.x, w * v.y, w * v.z, w * v.w};
    unsigned hh[4], ll[4];
#pragma unroll
    for (int i = 0; i < 4; i++) {
        __nv_bfloat16 hb = __float2bfloat16(a[i]);
        __nv_bfloat16 lb = __float2bfloat16(a[i] - __bfloat162float(hb));
        hh[i] = ((__nv_bfloat16_raw)hb).x;
        ll[i] = ((__nv_bfloat16_raw)lb).x;
    }
    uint2 ph = {hh[0] | (hh[1] << 16), hh[2] | (hh[3] << 16)};
    uint2 pl = {ll[0] | (ll[1] << 16), ll[2] | (ll[3] << 16)};
    ((uint2*)g_ah)[idx4] = ph;
    ((uint2*)g_al)[idx4] = pl;
}

// ---------------- expert GEMM2 + weighted bias + transpose -------------------
// R9 structure (2x64KB stages, occ 1), A-hoisted 3-term inner loop.
__global__ __launch_bounds__(256, 1) void k_egemm2(const float* __restrict__ b2,
                                                   float* __restrict__ out) {
    extern __shared__ char smc[];
    uint32_t sb = smem_u32(smc);
    int tid = threadIdx.x;
    int n0 = blockIdx.x * 128, m0 = blockIdx.y * 128;
    int warp = tid >> 5, lane = tid & 31;
    int wm = warp >> 1, wn = warp & 1;

    const __nv_bfloat16* ah = g_ah + (size_t)m0 * 128;
    const __nv_bfloat16* al = g_al + (size_t)m0 * 128;
    const __nv_bfloat16* bh = g_w2h + (size_t)n0 * 128;
    const __nv_bfloat16* bl = g_w2l + (size_t)n0 * 128;

    float acc[2][8][4];
#pragma unroll
    for (int i = 0; i < 2; i++)
#pragma unroll
        for (int j = 0; j < 8; j++)
#pragma unroll
            for (int q = 0; q < 4; q++) acc[i][j][q] = 0.f;

    int li = lane & 7, lm = lane >> 3;
    int a_row = (lm & 1) * 8 + li, a_cb = (lm >> 1) * 16;
    int b_row = (lm >> 1) * 8 + li, b_cb = (lm & 1) * 16;

#define LOADS2(S, K0) do {                                                      \
        uint32_t sbs = sb + (S) * 65536;                                        \
        const __nv_bfloat16* srcs[4] = {ah, al, bh, bl};                        \
        _Pragma("unroll")                                                       \
        for (int tt = 0; tt < 4; tt++) {                                        \
            const __nv_bfloat16* src = srcs[tt];                                \
            _Pragma("unroll")                                                   \
            for (int it = 0; it < 4; it++) {                                    \
                int idx = tid + it * 256;                                       \
                int r = idx >> 3, c16 = idx & 7;                                \
                const void* g = src + (size_t)r * 128 + (K0) + c16 * 8;         \
                uint32_t bo = (uint32_t)((r << 7) | (c16 << 4));                \
                bo ^= (bo >> 3) & 0x70;                                         \
                CP16(sbs + tt * 16384 + bo, g);                                 \
            }                                                                   \
        }                                                                       \
    } while (0)

    LOADS2(0, 0);
    CPCOMMIT();

    for (int kc = 0; kc < 2; kc++) {
        int s = kc & 1;
        if (kc < 1) {
            LOADS2(1, 64);
            CPCOMMIT();
            CPWAIT(1);
        } else {
            CPWAIT(0);
        }
        __syncthreads();

        uint32_t stg = sb + s * 65536;
#pragma unroll
        for (int ks = 0; ks < 4; ks++) {
            int kb = ks * 32;
            uint32_t afh[2][4], afl[2][4];
#pragma unroll
            for (int mi = 0; mi < 2; mi++) {
                int r = wm * 32 + mi * 16 + a_row;
                uint32_t cb = (uint32_t)(kb + a_cb);
                uint32_t off = (r << 7) + (cb ^ ((r & 7) << 4));
                ldm4(afh[mi], stg + off);
                ldm4(afl[mi], stg + 16384 + off);
            }
            uint32_t bfr[4][4];
#pragma unroll
            for (int p = 0; p < 4; p++) {
                int r = wn * 64 + p * 16 + b_row;
                uint32_t cb = (uint32_t)(kb + b_cb);
                ldm4(bfr[p], stg + 32768 + (r << 7) + (cb ^ ((r & 7) << 4)));
            }
#pragma unroll
            for (int mi = 0; mi < 2; mi++)
#pragma unroll
                for (int ni = 0; ni < 8; ni++) {
                    mma16816(acc[mi][ni], afh[mi],
                             bfr[ni >> 1][(ni & 1) * 2], bfr[ni >> 1][(ni & 1) * 2 + 1]);
                    mma16816(acc[mi][ni], afl[mi],
                             bfr[ni >> 1][(ni & 1) * 2], bfr[ni >> 1][(ni & 1) * 2 + 1]);
                }
#pragma unroll
            for (int p = 0; p < 4; p++) {
                int r = wn * 64 + p * 16 + b_row;
                uint32_t cb = (uint32_t)(kb + b_cb);
                ldm4(bfr[p], stg + 49152 + (r << 7) + (cb ^ ((r & 7) << 4)));
            }
#pragma unroll
            for (int mi = 0; mi < 2; mi++)
#pragma unroll
                for (int ni = 0; ni < 8; ni++)
                    mma16816(acc[mi][ni], afh[mi],
                             bfr[ni >> 1][(ni & 1) * 2], bfr[ni >> 1][(ni & 1) * 2 + 1]);
        }
        __syncthreads();
    }
#undef LOADS2

    // epilogue: stage to smem, add weighted bias, transposed store
    float* ot  = (float*)smc;            // 128 x 129
    float* b2s = ot + 128 * 129;         // 8 x 128
    float* srw = b2s + 1024;             // 256
    int*   sre = (int*)(srw + 256);      // 256

    int g = lane >> 2, tg = lane & 3;
#pragma unroll
    for (int mi = 0; mi < 2; mi++) {
        int rl = wm * 32 + mi * 16 + g;
#pragma unroll
        for (int ni = 0; ni < 8; ni++) {
            int cl = wn * 64 + ni * 8 + tg * 2;
            ot[rl * 129 + cl] = acc[mi][ni][0];
            ot[rl * 129 + cl + 1] = acc[mi][ni][1];
            ot[(rl + 8) * 129 + cl] = acc[mi][ni][2];
            ot[(rl + 8) * 129 + cl + 1] = acc[mi][ni][3];
        }
    }
    if (tid < 256) {
        sre[tid] = g_re[m0 * 2 + tid];
        srw[tid] = g_rw[m0 * 2 + tid];
    }
    for (int i = tid; i < 1024; i += 256) {
        int e = i >> 7, cl = i & 127;
        b2s[i] = b2[e * CC + n0 + cl];
    }
    __syncthreads();

    int c = tid >> 1, half = tid & 1;
    int batch = m0 >> 12, nb = m0 & (NNN - 1);
    float* ob = out + (size_t)batch * CC * NNN + (size_t)(n0 + c) * NNN + nb + half * 64;
#pragma unroll 2
    for (int tt4 = 0; tt4 < 64; tt4 += 4) {
        float4 v;
        float vv[4];
#pragma unroll
        for (int q = 0; q < 4; q++) {
            int ti = half * 64 + tt4 + q;
            float val = ot[ti * 129 + c];
            int ee0 = sre[2 * ti], ee1 = sre[2 * ti + 1];
            val += srw[2 * ti] * b2s[ee0 * 128 + c] + srw[2 * ti + 1] * b2s[ee1 * 128 + c];
            vv[q] = val;
        }
        v.x = vv[0]; v.y = vv[1]; v.z = vv[2]; v.w = vv[3];
        *(float4*)(ob + tt4) = v;
    }
}

// ---------------- load-balance loss -------------------------------------------
__global__ void k_lb(float* __restrict__ out, long long out_size) {
    if (threadIdx.x == 0 && out_size > (long long)BB * CC * NNN) {
        float s = 0.f;
#pragma unroll
        for (int e = 0; e < EE; e++) {
            float u = g_usage[e] * (1.0f / TT);
            s += u * u;
        }
        out[(size_t)BB * CC * NNN] = s * (float)EE;
    }
}

// ---------------- launch --------------------------------------------------------
extern "C" void kernel_launch(void* const* d_in, const int* in_sizes, int n_in,
                              void* d_out, int out_size) {
    const float* x     = (const float*)d_in[0];
    const float* wg1   = (const float*)d_in[1];
    const float* bg1   = (const float*)d_in[2];
    const float* gamma = (const float*)d_in[3];
    const float* beta  = (const float*)d_in[4];
    const float* wg2   = (const float*)d_in[5];
    const float* bg2   = (const float*)d_in[6];
    const float* w1    = (const float*)d_in[7];
    const float* b1    = (const float*)d_in[8];
    const float* w2    = (const float*)d_in[9];
    const float* b2    = (const float*)d_in[10];
    float* out = (float*)d_out;

    cudaFuncSetAttribute(k_gemm,   cudaFuncAttributeMaxDynamicSharedMemorySize, GSMEM);
    cudaFuncSetAttribute(k_egemm1, cudaFuncAttributeMaxDynamicSharedMemorySize, ESMEM);
    cudaFuncSetAttribute(k_egemm2, cudaFuncAttributeMaxDynamicSharedMemorySize, ESMEM);

    k_zero<<<1, 512>>>();
    {
        long long tot4 = ((long long)TT * CC + (long long)CC * CC) / 4;
        int nb = (int)((tot4 + 255) / 256);
        k_split<<<nb, 256>>>(x, wg1);
    }
    k_split2<<<512, 256>>>(w1, w2);
    dim3 gg(CC / 128, TT / 128);
    k_gemm<<<gg, 256, GSMEM>>>(bg1);
    k_egemm1<<<TT / 128, 256, ESMEM>>>(b1);
    k_route<<<TT / 32, 256>>>(gamma, beta, wg2, bg2);
    k_fix<<<256, 256>>>(x, wg1, gamma, beta, wg2, bg2);
    k_scale<<<TT * 128 / 4 / 256, 256>>>();
    dim3 g2(CC / 128, TT / 128);
    k_egemm2<<<g2, 256, ESMEM>>>(b2, out);
    k_lb<<<1, 32>>>(out, (long long)out_size);
}

// round 13
// speedup vs baseline: 1.1927x; 1.0232x over previous
#include <cuda_runtime.h>
#include <cuda_bf16.h>
#include <math.h>
#include <stdint.h>

#define TT   32768
#define CC   512
#define EE   8
#define HH   16
#define BB   8
#define NNN  4096
#define FIXCAP 8192

// ---------------- scratch (static device globals; no allocation) -------------
__device__ float g_h[(size_t)TT * CC];     // gate hidden, 64MB
__device__ float g_h1[(size_t)TT * 128];   // expert hidden (all experts), 16MB
__device__ int   g_re[TT * 2];
__device__ float g_rw[TT * 2];
__device__ float g_sum[CC];
__device__ float g_sumsq[CC];
__device__ float g_usage[EE];
__device__ int   g_nfix;
__device__ int   g_fix[FIXCAP];
__device__ __align__(16) __nv_bfloat16 g_xh[(size_t)TT * CC];
__device__ __align__(16) __nv_bfloat16 g_xl[(size_t)TT * CC];
__device__ __align__(16) __nv_bfloat16 g_wh[CC * CC];
__device__ __align__(16) __nv_bfloat16 g_wl[CC * CC];
__device__ __align__(16) __nv_bfloat16 g_w1h[128 * CC];   // W1cat^T [n=e*16+h][k=c]
__device__ __align__(16) __nv_bfloat16 g_w1l[128 * CC];
__device__ __align__(16) __nv_bfloat16 g_w2h[CC * 128];   // W2cat^T [n=c][k=e*16+h]
__device__ __align__(16) __nv_bfloat16 g_w2l[CC * 128];
__device__ __align__(16) __nv_bfloat16 g_ah[(size_t)TT * 128];  // h1scaled hi
__device__ __align__(16) __nv_bfloat16 g_al[(size_t)TT * 128];  // h1scaled lo

// ---------------- PTX helpers -------------------------------------------------
__device__ __forceinline__ uint32_t smem_u32(const void* p) {
    uint32_t a;
    asm("{ .reg .u64 t; cvta.to.shared.u64 t, %1; cvt.u32.u64 %0, t; }" : "=r"(a) : "l"(p));
    return a;
}
__device__ __forceinline__ void ldm4(uint32_t* r, uint32_t a) {
    asm volatile("ldmatrix.sync.aligned.m8n8.x4.shared.b16 {%0,%1,%2,%3}, [%4];"
                 : "=r"(r[0]), "=r"(r[1]), "=r"(r[2]), "=r"(r[3]) : "r"(a));
}
__device__ __forceinline__ void mma16816(float* d, const uint32_t* a,
                                         uint32_t b0, uint32_t b1) {
    asm volatile(
        "mma.sync.aligned.m16n8k16.row.col.f32.bf16.bf16.f32 "
        "{%0,%1,%2,%3}, {%4,%5,%6,%7}, {%8,%9}, {%0,%1,%2,%3};"
        : "+f"(d[0]), "+f"(d[1]), "+f"(d[2]), "+f"(d[3])
        : "r"(a[0]), "r"(a[1]), "r"(a[2]), "r"(a[3]), "r"(b0), "r"(b1));
}
#define CP16(dst, src) asm volatile("cp.async.cg.shared.global [%0], [%1], 16;" ::"r"(dst), "l"(src) : "memory")
#define CPCOMMIT()     asm volatile("cp.async.commit_group;" ::: "memory")
#define CPWAIT(n)      asm volatile("cp.async.wait_group %0;" ::"n"(n) : "memory")

// ---------------- zero accumulators ------------------------------------------
__global__ void k_zero() {
    int i = threadIdx.x;
    if (i < CC) { g_sum[i] = 0.f; g_sumsq[i] = 0.f; }
    if (i < EE) g_usage[i] = 0.f;
    if (i == 0) g_nfix = 0;
}

// ---------------- bf16 splits --------------------------------------------------
__global__ __launch_bounds__(256) void k_split(const float* __restrict__ x,
                                               const float* __restrict__ wg1) {
    size_t i4 = (size_t)blockIdx.x * 256 + threadIdx.x;
    const size_t nx = (size_t)TT * CC / 4, nw = (size_t)CC * CC / 4;
    const float* s; __nv_bfloat16 *dh, *dl; size_t o;
    if (i4 < nx)           { s = x;   o = i4;      dh = g_xh; dl = g_xl; }
    else if (i4 < nx + nw) { s = wg1; o = i4 - nx; dh = g_wh; dl = g_wl; }
    else return;
    float4 v = ((const float4*)s)[o];
    float a[4] = {v.x, v.y, v.z, v.w};
    unsigned hh[4], ll[4];
#pragma unroll
    for (int i = 0; i < 4; i++) {
        __nv_bfloat16 hb = __float2bfloat16(a[i]);
        __nv_bfloat16 lb = __float2bfloat16(a[i] - __bfloat162float(hb));
        hh[i] = ((__nv_bfloat16_raw)hb).x;
        ll[i] = ((__nv_bfloat16_raw)lb).x;
    }
    uint2 ph = {hh[0] | (hh[1] << 16), hh[2] | (hh[3] << 16)};
    uint2 pl = {ll[0] | (ll[1] << 16), ll[2] | (ll[3] << 16)};
    ((uint2*)dh)[o] = ph;
    ((uint2*)dl)[o] = pl;
}

// expert weight repack + split
__global__ __launch_bounds__(256) void k_split2(const float* __restrict__ w1,
                                                const float* __restrict__ w2) {
    int idx = blockIdx.x * 256 + threadIdx.x;
    if (idx < 65536) {
        int e = idx >> 13, r = idx & 8191, c = r >> 4, h = r & 15;
        float v = w1[idx];
        __nv_bfloat16 hb = __float2bfloat16(v);
        __nv_bfloat16 lb = __float2bfloat16(v - __bfloat162float(hb));
        int n = e * 16 + h;
        g_w1h[n * CC + c] = hb;
        g_w1l[n * CC + c] = lb;
    } else if (idx < 131072) {
        int j = idx - 65536;
        int e = j >> 13, r = j & 8191, h = r >> 9, c = r & 511;
        float v = w2[j];
        __nv_bfloat16 hb = __float2bfloat16(v);
        __nv_bfloat16 lb = __float2bfloat16(v - __bfloat162float(hb));
        int n = e * 16 + h;
        g_w2h[c * 128 + n] = hb;
        g_w2l[c * 128 + n] = lb;
    }
}

// ---------------- gate GEMM1 (HMMA, 2-term, cp.async 2-stage) -----------------
// A fragments hoisted across the two term pairs; B frags reuse one register set.
#define STG 49152
#define GSMEM (2 * STG)

__global__ __launch_bounds__(256, 2) void k_gemm(const float* __restrict__ bg1) {
    extern __shared__ char smc[];
    uint32_t sb = smem_u32(smc);
    int tid = threadIdx.x;
    int n0 = blockIdx.x * 128, m0 = blockIdx.y * 128;
    int warp = tid >> 5, lane = tid & 31;
    int wm = warp >> 1, wn = warp & 1;

    const __nv_bfloat16* xs  = g_xh + (size_t)m0 * CC;
    const __nv_bfloat16* whs = g_wh + (size_t)n0 * CC;
    const __nv_bfloat16* wls = g_wl + (size_t)n0 * CC;

    float acc[2][8][4];
#pragma unroll
    for (int i = 0; i < 2; i++)
#pragma unroll
        for (int j = 0; j < 8; j++)
#pragma unroll
            for (int q = 0; q < 4; q++) acc[i][j][q] = 0.f;

    int li = lane & 7, lm = lane >> 3;
    int a_row = (lm & 1) * 8 + li, a_cb = (lm >> 1) * 16;
    int b_row = (lm >> 1) * 8 + li, b_cb = (lm & 1) * 16;

#define LOADSTAGE(S, K0) do {                                                   \
        uint32_t sbs = sb + (S) * STG;                                          \
        const __nv_bfloat16* srcs[3] = {xs, whs, wls};                          \
        _Pragma("unroll")                                                       \
        for (int tt = 0; tt < 3; tt++) {                                        \
            const __nv_bfloat16* src = srcs[tt];                                \
            _Pragma("unroll")                                                   \
            for (int it = 0; it < 4; it++) {                                    \
                int idx = tid + it * 256;                                       \
                int r = idx >> 3, c16 = idx & 7;                                \
                const void* g = src + (size_t)r * CC + (K0) + c16 * 8;          \
                uint32_t bo = (uint32_t)((r << 7) | (c16 << 4));                \
                bo ^= (bo >> 3) & 0x70;                                         \
                CP16(sbs + tt * 16384 + bo, g);                                 \
            }                                                                   \
        }                                                                       \
    } while (0)

    LOADSTAGE(0, 0);
    CPCOMMIT();

    for (int kc = 0; kc < 8; kc++) {
        int s = kc & 1;
        if (kc < 7) {
            LOADSTAGE(s ^ 1, (kc + 1) * 64);
            CPCOMMIT();
            CPWAIT(1);
        } else {
            CPWAIT(0);
        }
        __syncthreads();

        uint32_t abase = sb + s * STG;
#pragma unroll
        for (int ks = 0; ks < 4; ks++) {
            int kb = ks * 32;
            uint32_t af[2][4];
#pragma unroll
            for (int mi = 0; mi < 2; mi++) {
                int r = wm * 32 + mi * 16 + a_row;
                uint32_t cb = (uint32_t)(kb + a_cb);
                ldm4(af[mi], abase + (r << 7) + (cb ^ ((r & 7) << 4)));
            }
            uint32_t bfr[4][4];
#pragma unroll
            for (int tp = 0; tp < 2; tp++) {
                uint32_t bbase = abase + 16384 + tp * 16384;
#pragma unroll
                for (int p = 0; p < 4; p++) {
                    int r = wn * 64 + p * 16 + b_row;
                    uint32_t cb = (uint32_t)(kb + b_cb);
                    ldm4(bfr[p], bbase + (r << 7) + (cb ^ ((r & 7) << 4)));
                }
#pragma unroll
                for (int mi = 0; mi < 2; mi++)
#pragma unroll
                    for (int ni = 0; ni < 8; ni++)
                        mma16816(acc[mi][ni], af[mi],
                                 bfr[ni >> 1][(ni & 1) * 2],
                                 bfr[ni >> 1][(ni & 1) * 2 + 1]);
            }
        }
        __syncthreads();
    }
#undef LOADSTAGE

    int g = lane >> 2, tg = lane & 3;
#pragma unroll
    for (int mi = 0; mi < 2; mi++) {
        int row = m0 + wm * 32 + mi * 16 + g;
#pragma unroll
        for (int ni = 0; ni < 8; ni++) {
            int col = n0 + wn * 64 + ni * 8 + tg * 2;
            float bx = bg1[col], by = bg1[col + 1];
            acc[mi][ni][0] += bx; acc[mi][ni][1] += by;
            acc[mi][ni][2] += bx; acc[mi][ni][3] += by;
            float2 v0 = {acc[mi][ni][0], acc[mi][ni][1]};
            float2 v1 = {acc[mi][ni][2], acc[mi][ni][3]};
            *(float2*)(g_h + (size_t)row * CC + col) = v0;
            *(float2*)(g_h + (size_t)(row + 8) * CC + col) = v1;
        }
    }

    float* ssum = (float*)smc;
    float* ssq  = (float*)(smc + 512);
    if (tid < 128) { ssum[tid] = 0.f; ssq[tid] = 0.f; }
    __syncthreads();
#pragma unroll
    for (int ni = 0; ni < 8; ni++) {
        int colr = wn * 64 + ni * 8 + tg * 2;
        float s0 = 0.f, s1 = 0.f, q0 = 0.f, q1 = 0.f;
#pragma unroll
        for (int mi = 0; mi < 2; mi++) {
            float a0 = acc[mi][ni][0], a1 = acc[mi][ni][1];
            float a2 = acc[mi][ni][2], a3 = acc[mi][ni][3];
            s0 += a0 + a2; s1 += a1 + a3;
            q0 += a0 * a0 + a2 * a2; q1 += a1 * a1 + a3 * a3;
        }
#pragma unroll
        for (int off = 4; off < 32; off <<= 1) {
            s0 += __shfl_xor_sync(0xffffffffu, s0, off);
            s1 += __shfl_xor_sync(0xffffffffu, s1, off);
            q0 += __shfl_xor_sync(0xffffffffu, q0, off);
            q1 += __shfl_xor_sync(0xffffffffu, q1, off);
        }
        if (g == 0) {
            atomicAdd(&ssum[colr], s0); atomicAdd(&ssum[colr + 1], s1);
            atomicAdd(&ssq[colr], q0);  atomicAdd(&ssq[colr + 1], q1);
        }
    }
    __syncthreads();
    if (tid < 128) {
        atomicAdd(&g_sum[n0 + tid], ssum[tid]);
        atomicAdd(&g_sumsq[n0 + tid], ssq[tid]);
    }
}

// ---------------- expert GEMM1: h1all = relu(x @ W1cat + b1) (3-term) --------
// BK=32 (64B rows, SW64 swizzle): stage = 4 x 8KB = 32KB, 2 stages = 64KB -> occ 2.
#define ESMEM1 65536

__global__ __launch_bounds__(256, 2) void k_egemm1(const float* __restrict__ b1) {
    extern __shared__ char smc[];
    uint32_t sb = smem_u32(smc);
    int tid = threadIdx.x;
    int m0 = blockIdx.x * 128;
    int warp = tid >> 5, lane = tid & 31;
    int wm = warp >> 1, wn = warp & 1;

    const __nv_bfloat16* ah = g_xh + (size_t)m0 * CC;
    const __nv_bfloat16* al = g_xl + (size_t)m0 * CC;

    float acc[2][8][4];
#pragma unroll
    for (int i = 0; i < 2; i++)
#pragma unroll
        for (int j = 0; j < 8; j++)
#pragma unroll
            for (int q = 0; q < 4; q++) acc[i][j][q] = 0.f;

    int li = lane & 7, lm = lane >> 3;
    int a_row = (lm & 1) * 8 + li, a_cb = (lm >> 1) * 16;
    int b_row = (lm >> 1) * 8 + li, b_cb = (lm & 1) * 16;

#define LOADS1(S, K0) do {                                                      \
        uint32_t sbs = sb + (S) * 32768;                                        \
        const __nv_bfloat16* srcs[4] = {ah, al, g_w1h, g_w1l};                  \
        _Pragma("unroll")                                                       \
        for (int tt = 0; tt < 4; tt++) {                                        \
            const __nv_bfloat16* src = srcs[tt];                                \
            _Pragma("unroll")                                                   \
            for (int it = 0; it < 2; it++) {                                    \
                int idx = tid + it * 256;                                       \
                int r = idx >> 2, c16 = idx & 3;                                \
                const void* g = src + (size_t)r * CC + (K0) + c16 * 8;          \
                uint32_t bo = (uint32_t)((r << 6) | (c16 << 4));                \
                bo ^= (bo >> 3) & 0x30;                                         \
                CP16(sbs + tt * 8192 + bo, g);                                  \
            }                                                                   \
        }                                                                       \
    } while (0)

    LOADS1(0, 0);
    CPCOMMIT();

    for (int kc = 0; kc < 16; kc++) {
        int s = kc & 1;
        if (kc < 15) {
            LOADS1(s ^ 1, (kc + 1) * 32);
            CPCOMMIT();
            CPWAIT(1);
        } else {
            CPWAIT(0);
        }
        __syncthreads();

        uint32_t stg = sb + s * 32768;
#pragma unroll
        for (int ks = 0; ks < 2; ks++) {
            int kb = ks * 32;
            uint32_t afh[2][4], afl[2][4];
#pragma unroll
            for (int mi = 0; mi < 2; mi++) {
                int r = wm * 32 + mi * 16 + a_row;
                uint32_t cb = (uint32_t)(kb + a_cb);
                uint32_t off = (r << 6) + (cb ^ (((r >> 1) & 3) << 4));
                ldm4(afh[mi], stg + off);
                ldm4(afl[mi], stg + 8192 + off);
            }
            uint32_t bfr[4][4];
            // Bh: used by AhBh and AlBh
#pragma unroll
            for (int p = 0; p < 4; p++) {
                int r = wn * 64 + p * 16 + b_row;
                uint32_t cb = (uint32_t)(kb + b_cb);
                ldm4(bfr[p], stg + 16384 + (r << 6) + (cb ^ (((r >> 1) & 3) << 4)));
            }
#pragma unroll
            for (int mi = 0; mi < 2; mi++)
#pragma unroll
                for (int ni = 0; ni < 8; ni++) {
                    mma16816(acc[mi][ni], afh[mi],
                             bfr[ni >> 1][(ni & 1) * 2], bfr[ni >> 1][(ni & 1) * 2 + 1]);
                    mma16816(acc[mi][ni], afl[mi],
                             bfr[ni >> 1][(ni & 1) * 2], bfr[ni >> 1][(ni & 1) * 2 + 1]);
                }
            // Bl: AhBl
#pragma unroll
            for (int p = 0; p < 4; p++) {
                int r = wn * 64 + p * 16 + b_row;
                uint32_t cb = (uint32_t)(kb + b_cb);
                ldm4(bfr[p], stg + 24576 + (r << 6) + (cb ^ (((r >> 1) & 3) << 4)));
            }
#pragma unroll
            for (int mi = 0; mi < 2; mi++)
#pragma unroll
                for (int ni = 0; ni < 8; ni++)
                    mma16816(acc[mi][ni], afh[mi],
                             bfr[ni >> 1][(ni & 1) * 2], bfr[ni >> 1][(ni & 1) * 2 + 1]);
        }
        __syncthreads();
    }
#undef LOADS1

    int g = lane >> 2, tg = lane & 3;
#pragma unroll
    for (int mi = 0; mi < 2; mi++) {
        int row = m0 + wm * 32 + mi * 16 + g;
#pragma unroll
        for (int ni = 0; ni < 8; ni++) {
            int col = wn * 64 + ni * 8 + tg * 2;
            float bx = b1[col], by = b1[col + 1];
            float2 v0 = {fmaxf(acc[mi][ni][0] + bx, 0.f), fmaxf(acc[mi][ni][1] + by, 0.f)};
            float2 v1 = {fmaxf(acc[mi][ni][2] + bx, 0.f), fmaxf(acc[mi][ni][3] + by, 0.f)};
            *(float2*)(g_h1 + (size_t)row * 128 + col) = v0;
            *(float2*)(g_h1 + (size_t)(row + 8) * 128 + col) = v1;
        }
    }
}

// ---------------- routing: stream h from gmem, warp-per-token ----------------
#define RSTR 516
__global__ __launch_bounds__(256) void k_route(const float* __restrict__ gamma,
                                               const float* __restrict__ beta,
                                               const float* __restrict__ wg2,
                                               const float* __restrict__ bg2) {
    __shared__ float ws[EE * RSTR];
    __shared__ float sc[CC], sh[CC];
    __shared__ float susage[EE];
    __shared__ float sbg2[EE];
    int tid = threadIdx.x, warp = tid >> 5, lane = tid & 31;

    if (tid < EE) { susage[tid] = 0.f; sbg2[tid] = bg2[tid]; }
    for (int c = tid; c < CC; c += 256) {
        float m = g_sum[c] * (1.0f / TT);
        float v = g_sumsq[c] * (1.0f / TT) - m * m;
        float rs = rsqrtf(v + 1e-5f);
        float s = gamma[c] * rs;
        sc[c] = s;
        sh[c] = beta[c] - m * s;
    }
    for (int i4 = tid; i4 < EE * 128; i4 += 256) {
        int e = i4 >> 7, c4 = (i4 & 127) << 2;
        float4 v = *(const float4*)(wg2 + e * CC + c4);
        *(float4*)(ws + e * RSTR + c4) = v;
    }
    __syncthreads();

#pragma unroll 1
    for (int j = 0; j < 4; j++) {
        int t = blockIdx.x * 32 + warp * 4 + j;
        float p[EE];
#pragma unroll
        for (int e = 0; e < EE; e++) p[e] = 0.f;
#pragma unroll 1
        for (int i = 0; i < 4; i++) {
            int c4 = i * 128 + lane * 4;
            float4 v = *(const float4*)(g_h + (size_t)t * CC + c4);
            float4 r;
            r.x = fmaxf(sc[c4 + 0] * v.x + sh[c4 + 0], 0.f);
            r.y = fmaxf(sc[c4 + 1] * v.y + sh[c4 + 1], 0.f);
            r.z = fmaxf(sc[c4 + 2] * v.z + sh[c4 + 2], 0.f);
            r.w = fmaxf(sc[c4 + 3] * v.w + sh[c4 + 3], 0.f);
#pragma unroll
            for (int e = 0; e < EE; e++) {
                float4 w = *(const float4*)(ws + e * RSTR + c4);
                p[e] += r.x * w.x + r.y * w.y + r.z * w.z + r.w * w.w;
            }
        }
#pragma unroll
        for (int e = 0; e < EE; e++)
#pragma unroll
            for (int off = 16; off; off >>= 1)
                p[e] += __shfl_xor_sync(0xffffffffu, p[e], off);

        if (lane == 0) {
            float l[EE];
#pragma unroll
            for (int e = 0; e < EE; e++) l[e] = p[e] + sbg2[e];
            int e0 = 0; float v0 = l[0];
#pragma unroll
            for (int e = 1; e < EE; e++) if (l[e] > v0) { v0 = l[e]; e0 = e; }
            int e1 = -1; float v1 = -1e30f;
#pragma unroll
            for (int e = 0; e < EE; e++) if (e != e0 && l[e] > v1) { v1 = l[e]; e1 = e; }
            float v2 = -1e30f;
#pragma unroll
            for (int e = 0; e < EE; e++) if (e != e0 && e != e1 && l[e] > v2) v2 = l[e];
            float ex = expf(v1 - v0);
            float inv = 1.f / (1.f + ex);
            g_re[t * 2] = e0; g_re[t * 2 + 1] = e1;
            g_rw[t * 2] = inv; g_rw[t * 2 + 1] = ex * inv;
            bool flagged = (v1 - v2) < 2.5e-3f;
            if (flagged) {
                int pos = atomicAdd(&g_nfix, 1);
                if (pos < FIXCAP) g_fix[pos] = t; else flagged = false;
            }
            if (!flagged) {
                atomicAdd(&susage[e0], inv);
                atomicAdd(&susage[e1], ex * inv);
            }
        }
    }
    __syncthreads();
    if (tid < EE) atomicAdd(&g_usage[tid], susage[tid]);
}

// ---------------- exact fp32 recompute for near-tie tokens -------------------
__global__ __launch_bounds__(256) void k_fix(const float* __restrict__ x,
                                             const float* __restrict__ wg1,
                                             const float* __restrict__ gamma,
                                             const float* __restrict__ beta,
                                             const float* __restrict__ wg2,
                                             const float* __restrict__ bg2) {
    __shared__ float xr[CC], rr[CC], lg[EE];
    int tid = threadIdx.x, w = tid >> 5, ln = tid & 31;
    int nf = g_nfix; if (nf > FIXCAP) nf = FIXCAP;
    for (int fi = blockIdx.x; fi < nf; fi += gridDim.x) {
        int t = g_fix[fi];
        __syncthreads();
        xr[tid] = x[(size_t)t * CC + tid];
        xr[tid + 256] = x[(size_t)t * CC + tid + 256];
        __syncthreads();
        for (int c = w; c < CC; c += 8) {
            const float* wr = wg1 + (size_t)c * CC;
            float a = 0.f;
#pragma unroll
            for (int j = 0; j < 16; j++) { int k = j * 32 + ln; a += xr[k] * wr[k]; }
#pragma unroll
            for (int off = 16; off; off >>= 1) a += __shfl_xor_sync(0xffffffffu, a, off);
            if (ln == 0) {
                float mu = g_sum[c] * (1.0f / TT);
                float var = g_sumsq[c] * (1.0f / TT) - mu * mu;
                rr[c] = fmaxf(gamma[c] * (a - mu) * rsqrtf(var + 1e-5f) + beta[c], 0.f);
            }
        }
        __syncthreads();
        if (w < EE) {
            const float* we = wg2 + w * CC;
            float a = 0.f;
#pragma unroll
            for (int j = 0; j < 16; j++) { int k = j * 32 + ln; a += rr[k] * we[k]; }
#pragma unroll
            for (int off = 16; off; off >>= 1) a += __shfl_xor_sync(0xffffffffu, a, off);
            if (ln == 0) lg[w] = a + bg2[w];
        }
        __syncthreads();
        if (tid == 0) {
            int e0 = 0; float v0 = lg[0];
#pragma unroll
            for (int e = 1; e < EE; e++) if (lg[e] > v0) { v0 = lg[e]; e0 = e; }
            int e1 = -1; float v1 = -1e30f;
#pragma unroll
            for (int e = 0; e < EE; e++) if (e != e0 && lg[e] > v1) { v1 = lg[e]; e1 = e; }
            float ex = expf(v1 - v0);
            float inv = 1.f / (1.f + ex);
            g_re[t * 2] = e0; g_re[t * 2 + 1] = e1;
            g_rw[t * 2] = inv; g_rw[t * 2 + 1] = ex * inv;
            atomicAdd(&g_usage[e0], inv);
            atomicAdd(&g_usage[e1], ex * inv);
        }
    }
}

// ---------------- scale h1 by routing weights, split to bf16 hi/lo ------------
__global__ __launch_bounds__(256) void k_scale() {
    int idx4 = blockIdx.x * 256 + threadIdx.x;
    int t = idx4 >> 5;
    int k4 = (idx4 & 31) << 2;
    int e = k4 >> 4;
    int e0 = __ldg(&g_re[t * 2]), e1 = __ldg(&g_re[t * 2 + 1]);
    float w = (e == e0) ? __ldg(&g_rw[t * 2]) : ((e == e1) ? __ldg(&g_rw[t * 2 + 1]) : 0.f);
    float4 v = *(const float4*)(g_h1 + (size_t)t * 128 + k4);
    float a[4] = {w * v.x, w * v.y, w * v.z, w * v.w};
    unsigned hh[4], ll[4];
#pragma unroll
    for (int i = 0; i < 4; i++) {
        __nv_bfloat16 hb = __float2bfloat16(a[i]);
        __nv_bfloat16 lb = __float2bfloat16(a[i] - __bfloat162float(hb));
        hh[i] = ((__nv_bfloat16_raw)hb).x;
        ll[i] = ((__nv_bfloat16_raw)lb).x;
    }
    uint2 ph = {hh[0] | (hh[1] << 16), hh[2] | (hh[3] << 16)};
    uint2 pl = {ll[0] | (ll[1] << 16), ll[2] | (ll[3] << 16)};
    ((uint2*)g_ah)[idx4] = ph;
    ((uint2*)g_al)[idx4] = pl;
}

// ---------------- expert GEMM2 + weighted bias + transpose -------------------
// BK=32 (SW64): stage 32KB x2 = 64KB; epilogue 72KB; occ 2.
#define ESMEM2 73728

__global__ __launch_bounds__(256, 2) void k_egemm2(const float* __restrict__ b2,
                                                   float* __restrict__ out) {
    extern __shared__ char smc[];
    uint32_t sb = smem_u32(smc);
    int tid = threadIdx.x;
    int n0 = blockIdx.x * 128, m0 = blockIdx.y * 128;
    int warp = tid >> 5, lane = tid & 31;
    int wm = warp >> 1, wn = warp & 1;

    const __nv_bfloat16* ah = g_ah + (size_t)m0 * 128;
    const __nv_bfloat16* al = g_al + (size_t)m0 * 128;
    const __nv_bfloat16* bh = g_w2h + (size_t)n0 * 128;
    const __nv_bfloat16* bl = g_w2l + (size_t)n0 * 128;

    float acc[2][8][4];
#pragma unroll
    for (int i = 0; i < 2; i++)
#pragma unroll
        for (int j = 0; j < 8; j++)
#pragma unroll
            for (int q = 0; q < 4; q++) acc[i][j][q] = 0.f;

    int li = lane & 7, lm = lane >> 3;
    int a_row = (lm & 1) * 8 + li, a_cb = (lm >> 1) * 16;
    int b_row = (lm >> 1) * 8 + li, b_cb = (lm & 1) * 16;

#define LOADS2(S, K0) do {                                                      \
        uint32_t sbs = sb + (S) * 32768;                                        \
        const __nv_bfloat16* srcs[4] = {ah, al, bh, bl};                        \
        _Pragma("unroll")                                                       \
        for (int tt = 0; tt < 4; tt++) {                                        \
            const __nv_bfloat16* src = srcs[tt];                                \
            _Pragma("unroll")                                                   \
            for (int it = 0; it < 2; it++) {                                    \
                int idx = tid + it * 256;                                       \
                int r = idx >> 2, c16 = idx & 3;                                \
                const void* g = src + (size_t)r * 128 + (K0) + c16 * 8;         \
                uint32_t bo = (uint32_t)((r << 6) | (c16 << 4));                \
                bo ^= (bo >> 3) & 0x30;                                         \
                CP16(sbs + tt * 8192 + bo, g);                                  \
            }                                                                   \
        }                                                                       \
    } while (0)

    LOADS2(0, 0);
    CPCOMMIT();

    for (int kc = 0; kc < 4; kc++) {
        int s = kc & 1;
        if (kc < 3) {
            LOADS2(s ^ 1, (kc + 1) * 32);
            CPCOMMIT();
            CPWAIT(1);
        } else {
            CPWAIT(0);
        }
        __syncthreads();

        uint32_t stg = sb + s * 32768;
#pragma unroll
        for (int ks = 0; ks < 2; ks++) {
            int kb = ks * 32;
            uint32_t afh[2][4], afl[2][4];
#pragma unroll
            for (int mi = 0; mi < 2; mi++) {
                int r = wm * 32 + mi * 16 + a_row;
                uint32_t cb = (uint32_t)(kb + a_cb);
                uint32_t off = (r << 6) + (cb ^ (((r >> 1) & 3) << 4));
                ldm4(afh[mi], stg + off);
                ldm4(afl[mi], stg + 8192 + off);
            }
            uint32_t bfr[4][4];
#pragma unroll
            for (int p = 0; p < 4; p++) {
                int r = wn * 64 + p * 16 + b_row;
                uint32_t cb = (uint32_t)(kb + b_cb);
                ldm4(bfr[p], stg + 16384 + (r << 6) + (cb ^ (((r >> 1) & 3) << 4)));
            }
#pragma unroll
            for (int mi = 0; mi < 2; mi++)
#pragma unroll
                for (int ni = 0; ni < 8; ni++) {
                    mma16816(acc[mi][ni], afh[mi],
                             bfr[ni >> 1][(ni & 1) * 2], bfr[ni >> 1][(ni & 1) * 2 + 1]);
                    mma16816(acc[mi][ni], afl[mi],
                             bfr[ni >> 1][(ni & 1) * 2], bfr[ni >> 1][(ni & 1) * 2 + 1]);
                }
#pragma unroll
            for (int p = 0; p < 4; p++) {
                int r = wn * 64 + p * 16 + b_row;
                uint32_t cb = (uint32_t)(kb + b_cb);
                ldm4(bfr[p], stg + 24576 + (r << 6) + (cb ^ (((r >> 1) & 3) << 4)));
            }
#pragma unroll
            for (int mi = 0; mi < 2; mi++)
#pragma unroll
                for (int ni = 0; ni < 8; ni++)
                    mma16816(acc[mi][ni], afh[mi],
                             bfr[ni >> 1][(ni & 1) * 2], bfr[ni >> 1][(ni & 1) * 2 + 1]);
        }
        __syncthreads();
    }
#undef LOADS2

    // epilogue: stage to smem, add weighted bias, transposed store
    float* ot  = (float*)smc;            // 128 x 129
    float* b2s = ot + 128 * 129;         // 8 x 128
    float* srw = b2s + 1024;             // 256
    int*   sre = (int*)(srw + 256);      // 256

    int g = lane >> 2, tg = lane & 3;
#pragma unroll
    for (int mi = 0; mi < 2; mi++) {
        int rl = wm * 32 + mi * 16 + g;
#pragma unroll
        for (int ni = 0; ni < 8; ni++) {
            int cl = wn * 64 + ni * 8 + tg * 2;
            ot[rl * 129 + cl] = acc[mi][ni][0];
            ot[rl * 129 + cl + 1] = acc[mi][ni][1];
            ot[(rl + 8) * 129 + cl] = acc[mi][ni][2];
            ot[(rl + 8) * 129 + cl + 1] = acc[mi][ni][3];
        }
    }
    if (tid < 256) {
        sre[tid] = g_re[m0 * 2 + tid];
        srw[tid] = g_rw[m0 * 2 + tid];
    }
    for (int i = tid; i < 1024; i += 256) {
        int e = i >> 7, cl = i & 127;
        b2s[i] = b2[e * CC + n0 + cl];
    }
    __syncthreads();

    int c = tid >> 1, half = tid & 1;
    int batch = m0 >> 12, nb = m0 & (NNN - 1);
    float* ob = out + (size_t)batch * CC * NNN + (size_t)(n0 + c) * NNN + nb + half * 64;
#pragma unroll 2
    for (int tt4 = 0; tt4 < 64; tt4 += 4) {
        float4 v;
        float vv[4];
#pragma unroll
        for (int q = 0; q < 4; q++) {
            int ti = half * 64 + tt4 + q;
            float val = ot[ti * 129 + c];
            int ee0 = sre[2 * ti], ee1 = sre[2 * ti + 1];
            val += srw[2 * ti] * b2s[ee0 * 128 + c] + srw[2 * ti + 1] * b2s[ee1 * 128 + c];
            vv[q] = val;
        }
        v.x = vv[0]; v.y = vv[1]; v.z = vv[2]; v.w = vv[3];
        *(float4*)(ob + tt4) = v;
    }
}

// ---------------- load-balance loss -------------------------------------------
__global__ void k_lb(float* __restrict__ out, long long out_size) {
    if (threadIdx.x == 0 && out_size > (long long)BB * CC * NNN) {
        float s = 0.f;
#pragma unroll
        for (int e = 0; e < EE; e++) {
            float u = g_usage[e] * (1.0f / TT);
            s += u * u;
        }
        out[(size_t)BB * CC * NNN] = s * (float)EE;
    }
}

// ---------------- launch --------------------------------------------------------
extern "C" void kernel_launch(void* const* d_in, const int* in_sizes, int n_in,
                              void* d_out, int out_size) {
    const float* x     = (const float*)d_in[0];
    const float* wg1   = (const float*)d_in[1];
    const float* bg1   = (const float*)d_in[2];
    const float* gamma = (const float*)d_in[3];
    const float* beta  = (const float*)d_in[4];
    const float* wg2   = (const float*)d_in[5];
    const float* bg2   = (const float*)d_in[6];
    const float* w1    = (const float*)d_in[7];
    const float* b1    = (const float*)d_in[8];
    const float* w2    = (const float*)d_in[9];
    const float* b2    = (const float*)d_in[10];
    float* out = (float*)d_out;

    cudaFuncSetAttribute(k_gemm,   cudaFuncAttributeMaxDynamicSharedMemorySize, GSMEM);
    cudaFuncSetAttribute(k_egemm1, cudaFuncAttributeMaxDynamicSharedMemorySize, ESMEM1);
    cudaFuncSetAttribute(k_egemm2, cudaFuncAttributeMaxDynamicSharedMemorySize, ESMEM2);

    k_zero<<<1, 512>>>();
    {
        long long tot4 = ((long long)TT * CC + (long long)CC * CC) / 4;
        int nb = (int)((tot4 + 255) / 256);
        k_split<<<nb, 256>>>(x, wg1);
    }
    k_split2<<<512, 256>>>(w1, w2);
    dim3 gg(CC / 128, TT / 128);
    k_gemm<<<gg, 256, GSMEM>>>(bg1);
    k_egemm1<<<TT / 128, 256, ESMEM1>>>(b1);
    k_route<<<TT / 32, 256>>>(gamma, beta, wg2, bg2);
    k_fix<<<256, 256>>>(x, wg1, gamma, beta, wg2, bg2);
    k_scale<<<TT * 128 / 4 / 256, 256>>>();
    dim3 g2(CC / 128, TT / 128);
    k_egemm2<<<g2, 256, ESMEM2>>>(b2, out);
    k_lb<<<1, 32>>>(out, (long long)out_size);
}

// round 15
// speedup vs baseline: 1.1988x; 1.0051x over previous
#include <cuda_runtime.h>
#include <cuda_bf16.h>
#include <math.h>
#include <stdint.h>

#define TT   32768
#define CC   512
#define EE   8
#define HH   16
#define BB   8
#define NNN  4096
#define FIXCAP 8192

// ---------------- scratch (static device globals; no allocation) -------------
__device__ float g_h[(size_t)TT * CC];     // gate hidden, 64MB
__device__ float g_h1[(size_t)TT * 128];   // expert hidden (all experts), 16MB
__device__ int   g_re[TT * 2];
__device__ float g_rw[TT * 2];
__device__ float g_sum[CC];
__device__ float g_sumsq[CC];
__device__ float g_usage[EE];
__device__ int   g_nfix;
__device__ int   g_fix[FIXCAP];
__device__ __align__(16) __nv_bfloat16 g_xh[(size_t)TT * CC];
__device__ __align__(16) __nv_bfloat16 g_xl[(size_t)TT * CC];
__device__ __align__(16) __nv_bfloat16 g_wh[CC * CC];
__device__ __align__(16) __nv_bfloat16 g_wl[CC * CC];
__device__ __align__(16) __nv_bfloat16 g_w1h[128 * CC];   // W1cat^T [n=e*16+h][k=c]
__device__ __align__(16) __nv_bfloat16 g_w1l[128 * CC];
__device__ __align__(16) __nv_bfloat16 g_w2h[CC * 128];   // W2cat^T [n=c][k=e*16+h]
__device__ __align__(16) __nv_bfloat16 g_w2l[CC * 128];
__device__ __align__(16) __nv_bfloat16 g_ah[(size_t)TT * 128];  // h1scaled hi
__device__ __align__(16) __nv_bfloat16 g_al[(size_t)TT * 128];  // h1scaled lo

// ---------------- PTX helpers -------------------------------------------------
__device__ __forceinline__ uint32_t smem_u32(const void* p) {
    uint32_t a;
    asm("{ .reg .u64 t; cvta.to.shared.u64 t, %1; cvt.u32.u64 %0, t; }" : "=r"(a) : "l"(p));
    return a;
}
__device__ __forceinline__ void ldm4(uint32_t* r, uint32_t a) {
    asm volatile("ldmatrix.sync.aligned.m8n8.x4.shared.b16 {%0,%1,%2,%3}, [%4];"
                 : "=r"(r[0]), "=r"(r[1]), "=r"(r[2]), "=r"(r[3]) : "r"(a));
}
__device__ __forceinline__ void mma16816(float* d, const uint32_t* a,
                                         uint32_t b0, uint32_t b1) {
    asm volatile(
        "mma.sync.aligned.m16n8k16.row.col.f32.bf16.bf16.f32 "
        "{%0,%1,%2,%3}, {%4,%5,%6,%7}, {%8,%9}, {%0,%1,%2,%3};"
        : "+f"(d[0]), "+f"(d[1]), "+f"(d[2]), "+f"(d[3])
        : "r"(a[0]), "r"(a[1]), "r"(a[2]), "r"(a[3]), "r"(b0), "r"(b1));
}
#define CP16(dst, src) asm volatile("cp.async.cg.shared.global [%0], [%1], 16;" ::"r"(dst), "l"(src) : "memory")
#define CPCOMMIT()     asm volatile("cp.async.commit_group;" ::: "memory")
#define CPWAIT(n)      asm volatile("cp.async.wait_group %0;" ::"n"(n) : "memory")

// ---------------- zero accumulators ------------------------------------------
__global__ void k_zero() {
    int i = threadIdx.x;
    if (i < CC) { g_sum[i] = 0.f; g_sumsq[i] = 0.f; }
    if (i < EE) g_usage[i] = 0.f;
    if (i == 0) g_nfix = 0;
}

// ---------------- bf16 splits --------------------------------------------------
__global__ __launch_bounds__(256) void k_split(const float* __restrict__ x,
                                               const float* __restrict__ wg1) {
    size_t i4 = (size_t)blockIdx.x * 256 + threadIdx.x;
    const size_t nx = (size_t)TT * CC / 4, nw = (size_t)CC * CC / 4;
    const float* s; __nv_bfloat16 *dh, *dl; size_t o;
    if (i4 < nx)           { s = x;   o = i4;      dh = g_xh; dl = g_xl; }
    else if (i4 < nx + nw) { s = wg1; o = i4 - nx; dh = g_wh; dl = g_wl; }
    else return;
    float4 v = ((const float4*)s)[o];
    float a[4] = {v.x, v.y, v.z, v.w};
    unsigned hh[4], ll[4];
#pragma unroll
    for (int i = 0; i < 4; i++) {
        __nv_bfloat16 hb = __float2bfloat16(a[i]);
        __nv_bfloat16 lb = __float2bfloat16(a[i] - __bfloat162float(hb));
        hh[i] = ((__nv_bfloat16_raw)hb).x;
        ll[i] = ((__nv_bfloat16_raw)lb).x;
    }
    uint2 ph = {hh[0] | (hh[1] << 16), hh[2] | (hh[3] << 16)};
    uint2 pl = {ll[0] | (ll[1] << 16), ll[2] | (ll[3] << 16)};
    ((uint2*)dh)[o] = ph;
    ((uint2*)dl)[o] = pl;
}

// expert weight repack + split
__global__ __launch_bounds__(256) void k_split2(const float* __restrict__ w1,
                                                const float* __restrict__ w2) {
    int idx = blockIdx.x * 256 + threadIdx.x;
    if (idx < 65536) {
        int e = idx >> 13, r = idx & 8191, c = r >> 4, h = r & 15;
        float v = w1[idx];
        __nv_bfloat16 hb = __float2bfloat16(v);
        __nv_bfloat16 lb = __float2bfloat16(v - __bfloat162float(hb));
        int n = e * 16 + h;
        g_w1h[n * CC + c] = hb;
        g_w1l[n * CC + c] = lb;
    } else if (idx < 131072) {
        int j = idx - 65536;
        int e = j >> 13, r = j & 8191, h = r >> 9, c = r & 511;
        float v = w2[j];
        __nv_bfloat16 hb = __float2bfloat16(v);
        __nv_bfloat16 lb = __float2bfloat16(v - __bfloat162float(hb));
        int n = e * 16 + h;
        g_w2h[c * 128 + n] = hb;
        g_w2l[c * 128 + n] = lb;
    }
}

// ---------------- fused gate GEMM + expert GEMM1 (one launch) -----------------
// blocks [0,256):    egemm1: h1all = relu(x @ W1cat + b1), 3-term, BK=32/SW64
// blocks [256,1280): gate gemm: h = xh@(wh+wl)^T + bg1 + BN stats, BK=64/SW128
#define STG 49152
#define GGSMEM 98304

__global__ __launch_bounds__(256, 2) void k_gg(const float* __restrict__ bg1,
                                               const float* __restrict__ b1) {
    extern __shared__ char smc[];
    uint32_t sb = smem_u32(smc);
    int tid = threadIdx.x;
    int warp = tid >> 5, lane = tid & 31;
    int wm = warp >> 1, wn = warp & 1;
    int li = lane & 7, lm = lane >> 3;
    int a_row = (lm & 1) * 8 + li, a_cb = (lm >> 1) * 16;
    int b_row = (lm >> 1) * 8 + li, b_cb = (lm & 1) * 16;

    float acc[2][8][4];
#pragma unroll
    for (int i = 0; i < 2; i++)
#pragma unroll
        for (int j = 0; j < 8; j++)
#pragma unroll
            for (int q = 0; q < 4; q++) acc[i][j][q] = 0.f;

    if (blockIdx.x < 256) {
        // ================= expert GEMM1 =================
        int m0 = blockIdx.x * 128;
        const __nv_bfloat16* ah = g_xh + (size_t)m0 * CC;
        const __nv_bfloat16* al = g_xl + (size_t)m0 * CC;

#define LOADS1(S, K0) do {                                                      \
        uint32_t sbs = sb + (S) * 32768;                                        \
        const __nv_bfloat16* srcs[4] = {ah, al, g_w1h, g_w1l};                  \
        _Pragma("unroll")                                                       \
        for (int tt = 0; tt < 4; tt++) {                                        \
            const __nv_bfloat16* src = srcs[tt];                                \
            _Pragma("unroll")                                                   \
            for (int it = 0; it < 2; it++) {                                    \
                int idx = tid + it * 256;                                       \
                int r = idx >> 2, c16 = idx & 3;                                \
                const void* g = src + (size_t)r * CC + (K0) + c16 * 8;          \
                uint32_t bo = (uint32_t)((r << 6) | (c16 << 4));                \
                bo ^= (bo >> 3) & 0x30;                                         \
                CP16(sbs + tt * 8192 + bo, g);                                  \
            }                                                                   \
        }                                                                       \
    } while (0)

        LOADS1(0, 0);
        CPCOMMIT();

        for (int kc = 0; kc < 16; kc++) {
            int s = kc & 1;
            if (kc < 15) {
                LOADS1(s ^ 1, (kc + 1) * 32);
                CPCOMMIT();
                CPWAIT(1);
            } else {
                CPWAIT(0);
            }
            __syncthreads();

            uint32_t stg = sb + s * 32768;
#pragma unroll
            for (int ks = 0; ks < 2; ks++) {
                int kb = ks * 32;
                uint32_t afh[2][4], afl[2][4];
#pragma unroll
                for (int mi = 0; mi < 2; mi++) {
                    int r = wm * 32 + mi * 16 + a_row;
                    uint32_t cb = (uint32_t)(kb + a_cb);
                    uint32_t off = (r << 6) + (cb ^ (((r >> 1) & 3) << 4));
                    ldm4(afh[mi], stg + off);
                    ldm4(afl[mi], stg + 8192 + off);
                }
                uint32_t bfr[4][4];
#pragma unroll
                for (int p = 0; p < 4; p++) {
                    int r = wn * 64 + p * 16 + b_row;
                    uint32_t cb = (uint32_t)(kb + b_cb);
                    ldm4(bfr[p], stg + 16384 + (r << 6) + (cb ^ (((r >> 1) & 3) << 4)));
                }
#pragma unroll
                for (int mi = 0; mi < 2; mi++)
#pragma unroll
                    for (int ni = 0; ni < 8; ni++) {
                        mma16816(acc[mi][ni], afh[mi],
                                 bfr[ni >> 1][(ni & 1) * 2], bfr[ni >> 1][(ni & 1) * 2 + 1]);
                        mma16816(acc[mi][ni], afl[mi],
                                 bfr[ni >> 1][(ni & 1) * 2], bfr[ni >> 1][(ni & 1) * 2 + 1]);
                    }
#pragma unroll
                for (int p = 0; p < 4; p++) {
                    int r = wn * 64 + p * 16 + b_row;
                    uint32_t cb = (uint32_t)(kb + b_cb);
                    ldm4(bfr[p], stg + 24576 + (r << 6) + (cb ^ (((r >> 1) & 3) << 4)));
                }
#pragma unroll
                for (int mi = 0; mi < 2; mi++)
#pragma unroll
                    for (int ni = 0; ni < 8; ni++)
                        mma16816(acc[mi][ni], afh[mi],
                                 bfr[ni >> 1][(ni & 1) * 2], bfr[ni >> 1][(ni & 1) * 2 + 1]);
            }
            __syncthreads();
        }
#undef LOADS1

        int g = lane >> 2, tg = lane & 3;
#pragma unroll
        for (int mi = 0; mi < 2; mi++) {
            int row = m0 + wm * 32 + mi * 16 + g;
#pragma unroll
            for (int ni = 0; ni < 8; ni++) {
                int col = wn * 64 + ni * 8 + tg * 2;
                float bx = b1[col], by = b1[col + 1];
                float2 v0 = {fmaxf(acc[mi][ni][0] + bx, 0.f), fmaxf(acc[mi][ni][1] + by, 0.f)};
                float2 v1 = {fmaxf(acc[mi][ni][2] + bx, 0.f), fmaxf(acc[mi][ni][3] + by, 0.f)};
                *(float2*)(g_h1 + (size_t)row * 128 + col) = v0;
                *(float2*)(g_h1 + (size_t)(row + 8) * 128 + col) = v1;
            }
        }
    } else {
        // ================= gate GEMM (2-term) =================
        int bid = blockIdx.x - 256;
        int n0 = (bid & 3) * 128, m0 = (bid >> 2) * 128;
        const __nv_bfloat16* xs  = g_xh + (size_t)m0 * CC;
        const __nv_bfloat16* whs = g_wh + (size_t)n0 * CC;
        const __nv_bfloat16* wls = g_wl + (size_t)n0 * CC;

#define LOADSTAGE(S, K0) do {                                                   \
        uint32_t sbs = sb + (S) * STG;                                          \
        const __nv_bfloat16* srcs[3] = {xs, whs, wls};                          \
        _Pragma("unroll")                                                       \
        for (int tt = 0; tt < 3; tt++) {                                        \
            const __nv_bfloat16* src = srcs[tt];                                \
            _Pragma("unroll")                                                   \
            for (int it = 0; it < 4; it++) {                                    \
                int idx = tid + it * 256;                                       \
                int r = idx >> 3, c16 = idx & 7;                                \
                const void* g = src + (size_t)r * CC + (K0) + c16 * 8;          \
                uint32_t bo = (uint32_t)((r << 7) | (c16 << 4));                \
                bo ^= (bo >> 3) & 0x70;                                         \
                CP16(sbs + tt * 16384 + bo, g);                                 \
            }                                                                   \
        }                                                                       \
    } while (0)

        LOADSTAGE(0, 0);
        CPCOMMIT();

        for (int kc = 0; kc < 8; kc++) {
            int s = kc & 1;
            if (kc < 7) {
                LOADSTAGE(s ^ 1, (kc + 1) * 64);
                CPCOMMIT();
                CPWAIT(1);
            } else {
                CPWAIT(0);
            }
            __syncthreads();

            uint32_t abase = sb + s * STG;
#pragma unroll
            for (int ks = 0; ks < 4; ks++) {
                int kb = ks * 32;
                uint32_t af[2][4];
#pragma unroll
                for (int mi = 0; mi < 2; mi++) {
                    int r = wm * 32 + mi * 16 + a_row;
                    uint32_t cb = (uint32_t)(kb + a_cb);
                    ldm4(af[mi], abase + (r << 7) + (cb ^ ((r & 7) << 4)));
                }
                uint32_t bfr[4][4];
#pragma unroll
                for (int tp = 0; tp < 2; tp++) {
                    uint32_t bbase = abase + 16384 + tp * 16384;
#pragma unroll
                    for (int p = 0; p < 4; p++) {
                        int r = wn * 64 + p * 16 + b_row;
                        uint32_t cb = (uint32_t)(kb + b_cb);
                        ldm4(bfr[p], bbase + (r << 7) + (cb ^ ((r & 7) << 4)));
                    }
#pragma unroll
                    for (int mi = 0; mi < 2; mi++)
#pragma unroll
                        for (int ni = 0; ni < 8; ni++)
                            mma16816(acc[mi][ni], af[mi],
                                     bfr[ni >> 1][(ni & 1) * 2],
                                     bfr[ni >> 1][(ni & 1) * 2 + 1]);
                }
            }
            __syncthreads();
        }
#undef LOADSTAGE

        int g = lane >> 2, tg = lane & 3;
#pragma unroll
        for (int mi = 0; mi < 2; mi++) {
            int row = m0 + wm * 32 + mi * 16 + g;
#pragma unroll
            for (int ni = 0; ni < 8; ni++) {
                int col = n0 + wn * 64 + ni * 8 + tg * 2;
                float bx = bg1[col], by = bg1[col + 1];
                acc[mi][ni][0] += bx; acc[mi][ni][1] += by;
                acc[mi][ni][2] += bx; acc[mi][ni][3] += by;
                float2 v0 = {acc[mi][ni][0], acc[mi][ni][1]};
                float2 v1 = {acc[mi][ni][2], acc[mi][ni][3]};
                *(float2*)(g_h + (size_t)row * CC + col) = v0;
                *(float2*)(g_h + (size_t)(row + 8) * CC + col) = v1;
            }
        }

        float* ssum = (float*)smc;
        float* ssq  = (float*)(smc + 512);
        if (tid < 128) { ssum[tid] = 0.f; ssq[tid] = 0.f; }
        __syncthreads();
#pragma unroll
        for (int ni = 0; ni < 8; ni++) {
            int colr = wn * 64 + ni * 8 + tg * 2;
            float s0 = 0.f, s1 = 0.f, q0 = 0.f, q1 = 0.f;
#pragma unroll
            for (int mi = 0; mi < 2; mi++) {
                float a0 = acc[mi][ni][0], a1 = acc[mi][ni][1];
                float a2 = acc[mi][ni][2], a3 = acc[mi][ni][3];
                s0 += a0 + a2; s1 += a1 + a3;
                q0 += a0 * a0 + a2 * a2; q1 += a1 * a1 + a3 * a3;
            }
#pragma unroll
            for (int off = 4; off < 32; off <<= 1) {
                s0 += __shfl_xor_sync(0xffffffffu, s0, off);
                s1 += __shfl_xor_sync(0xffffffffu, s1, off);
                q0 += __shfl_xor_sync(0xffffffffu, q0, off);
                q1 += __shfl_xor_sync(0xffffffffu, q1, off);
            }
            if (g == 0) {
                atomicAdd(&ssum[colr], s0); atomicAdd(&ssum[colr + 1], s1);
                atomicAdd(&ssq[colr], q0);  atomicAdd(&ssq[colr + 1], q1);
            }
        }
        __syncthreads();
        if (tid < 128) {
            atomicAdd(&g_sum[n0 + tid], ssum[tid]);
            atomicAdd(&g_sumsq[n0 + tid], ssq[tid]);
        }
    }
}

// ---------------- routing: stream h from gmem, warp-per-token ----------------
#define RSTR 516
__global__ __launch_bounds__(256) void k_route(const float* __restrict__ gamma,
                                               const float* __restrict__ beta,
                                               const float* __restrict__ wg2,
                                               const float* __restrict__ bg2) {
    __shared__ float ws[EE * RSTR];
    __shared__ float sc[CC], sh[CC];
    __shared__ float susage[EE];
    __shared__ float sbg2[EE];
    int tid = threadIdx.x, warp = tid >> 5, lane = tid & 31;

    if (tid < EE) { susage[tid] = 0.f; sbg2[tid] = bg2[tid]; }
    for (int c = tid; c < CC; c += 256) {
        float m = g_sum[c] * (1.0f / TT);
        float v = g_sumsq[c] * (1.0f / TT) - m * m;
        float rs = rsqrtf(v + 1e-5f);
        float s = gamma[c] * rs;
        sc[c] = s;
        sh[c] = beta[c] - m * s;
    }
    for (int i4 = tid; i4 < EE * 128; i4 += 256) {
        int e = i4 >> 7, c4 = (i4 & 127) << 2;
        float4 v = *(const float4*)(wg2 + e * CC + c4);
        *(float4*)(ws + e * RSTR + c4) = v;
    }
    __syncthreads();

#pragma unroll 1
    for (int j = 0; j < 4; j++) {
        int t = blockIdx.x * 32 + warp * 4 + j;
        float p[EE];
#pragma unroll
        for (int e = 0; e < EE; e++) p[e] = 0.f;
#pragma unroll 1
        for (int i = 0; i < 4; i++) {
            int c4 = i * 128 + lane * 4;
            float4 v = *(const float4*)(g_h + (size_t)t * CC + c4);
            float4 r;
            r.x = fmaxf(sc[c4 + 0] * v.x + sh[c4 + 0], 0.f);
            r.y = fmaxf(sc[c4 + 1] * v.y + sh[c4 + 1], 0.f);
            r.z = fmaxf(sc[c4 + 2] * v.z + sh[c4 + 2], 0.f);
            r.w = fmaxf(sc[c4 + 3] * v.w + sh[c4 + 3], 0.f);
#pragma unroll
            for (int e = 0; e < EE; e++) {
                float4 w = *(const float4*)(ws + e * RSTR + c4);
                p[e] += r.x * w.x + r.y * w.y + r.z * w.z + r.w * w.w;
            }
        }
#pragma unroll
        for (int e = 0; e < EE; e++)
#pragma unroll
            for (int off = 16; off; off >>= 1)
                p[e] += __shfl_xor_sync(0xffffffffu, p[e], off);

        if (lane == 0) {
            float l[EE];
#pragma unroll
            for (int e = 0; e < EE; e++) l[e] = p[e] + sbg2[e];
            int e0 = 0; float v0 = l[0];
#pragma unroll
            for (int e = 1; e < EE; e++) if (l[e] > v0) { v0 = l[e]; e0 = e; }
            int e1 = -1; float v1 = -1e30f;
#pragma unroll
            for (int e = 0; e < EE; e++) if (e != e0 && l[e] > v1) { v1 = l[e]; e1 = e; }
            float v2 = -1e30f;
#pragma unroll
            for (int e = 0; e < EE; e++) if (e != e0 && e != e1 && l[e] > v2) v2 = l[e];
            float ex = expf(v1 - v0);
            float inv = 1.f / (1.f + ex);
            g_re[t * 2] = e0; g_re[t * 2 + 1] = e1;
            g_rw[t * 2] = inv; g_rw[t * 2 + 1] = ex * inv;
            bool flagged = (v1 - v2) < 2.5e-3f;
            if (flagged) {
                int pos = atomicAdd(&g_nfix, 1);
                if (pos < FIXCAP) g_fix[pos] = t; else flagged = false;
            }
            if (!flagged) {
                atomicAdd(&susage[e0], inv);
                atomicAdd(&susage[e1], ex * inv);
            }
        }
    }
    __syncthreads();
    if (tid < EE) atomicAdd(&g_usage[tid], susage[tid]);
}

// ---------------- exact fp32 recompute for near-tie tokens -------------------
__global__ __launch_bounds__(256) void k_fix(const float* __restrict__ x,
                                             const float* __restrict__ wg1,
                                             const float* __restrict__ gamma,
                                             const float* __restrict__ beta,
                                             const float* __restrict__ wg2,
                                             const float* __restrict__ bg2) {
    __shared__ float xr[CC], rr[CC], lg[EE];
    int tid = threadIdx.x, w = tid >> 5, ln = tid & 31;
    int nf = g_nfix; if (nf > FIXCAP) nf = FIXCAP;
    for (int fi = blockIdx.x; fi < nf; fi += gridDim.x) {
        int t = g_fix[fi];
        __syncthreads();
        xr[tid] = x[(size_t)t * CC + tid];
        xr[tid + 256] = x[(size_t)t * CC + tid + 256];
        __syncthreads();
        for (int c = w; c < CC; c += 8) {
            const float* wr = wg1 + (size_t)c * CC;
            float a = 0.f;
#pragma unroll
            for (int j = 0; j < 16; j++) { int k = j * 32 + ln; a += xr[k] * wr[k]; }
#pragma unroll
            for (int off = 16; off; off >>= 1) a += __shfl_xor_sync(0xffffffffu, a, off);
            if (ln == 0) {
                float mu = g_sum[c] * (1.0f / TT);
                float var = g_sumsq[c] * (1.0f / TT) - mu * mu;
                rr[c] = fmaxf(gamma[c] * (a - mu) * rsqrtf(var + 1e-5f) + beta[c], 0.f);
            }
        }
        __syncthreads();
        if (w < EE) {
            const float* we = wg2 + w * CC;
            float a = 0.f;
#pragma unroll
            for (int j = 0; j < 16; j++) { int k = j * 32 + ln; a += rr[k] * we[k]; }
#pragma unroll
            for (int off = 16; off; off >>= 1) a += __shfl_xor_sync(0xffffffffu, a, off);
            if (ln == 0) lg[w] = a + bg2[w];
        }
        __syncthreads();
        if (tid == 0) {
            int e0 = 0; float v0 = lg[0];
#pragma unroll
            for (int e = 1; e < EE; e++) if (lg[e] > v0) { v0 = lg[e]; e0 = e; }
            int e1 = -1; float v1 = -1e30f;
#pragma unroll
            for (int e = 0; e < EE; e++) if (e != e0 && lg[e] > v1) { v1 = lg[e]; e1 = e; }
            float ex = expf(v1 - v0);
            float inv = 1.f / (1.f + ex);
            g_re[t * 2] = e0; g_re[t * 2 + 1] = e1;
            g_rw[t * 2] = inv; g_rw[t * 2 + 1] = ex * inv;
            atomicAdd(&g_usage[e0], inv);
            atomicAdd(&g_usage[e1], ex * inv);
        }
    }
}

// ---------------- scale h1 by routing weights, split to bf16 hi/lo ------------
__global__ __launch_bounds__(256) void k_scale() {
    int idx4 = blockIdx.x * 256 + threadIdx.x;
    int t = idx4 >> 5;
    int k4 = (idx4 & 31) << 2;
    int e = k4 >> 4;
    int e0 = __ldg(&g_re[t * 2]), e1 = __ldg(&g_re[t * 2 + 1]);
    float w = (e == e0) ? __ldg(&g_rw[t * 2]) : ((e == e1) ? __ldg(&g_rw[t * 2 + 1]) : 0.f);
    float4 v = *(const float4*)(g_h1 + (size_t)t * 128 + k4);
    float a[4] = {w * v.x, w * v.y, w * v.z, w * v.w};
    unsigned hh[4], ll[4];
#pragma unroll
    for (int i = 0; i < 4; i++) {
        __nv_bfloat16 hb = __float2bfloat16(a[i]);
        __nv_bfloat16 lb = __float2bfloat16(a[i] - __bfloat162float(hb));
        hh[i] = ((__nv_bfloat16_raw)hb).x;
        ll[i] = ((__nv_bfloat16_raw)lb).x;
    }
    uint2 ph = {hh[0] | (hh[1] << 16), hh[2] | (hh[3] << 16)};
    uint2 pl = {ll[0] | (ll[1] << 16), ll[2] | (ll[3] << 16)};
    ((uint2*)g_ah)[idx4] = ph;
    ((uint2*)g_al)[idx4] = pl;
}

// ---------------- expert GEMM2 + weighted bias + transpose -------------------
// BK=32 (SW64): stage 32KB x2 = 64KB; epilogue 72KB; occ 2.
#define ESMEM2 73728

__global__ __launch_bounds__(256, 2) void k_egemm2(const float* __restrict__ b2,
                                                   float* __restrict__ out) {
    extern __shared__ char smc[];
    uint32_t sb = smem_u32(smc);
    int tid = threadIdx.x;
    int n0 = blockIdx.x * 128, m0 = blockIdx.y * 128;
    int warp = tid >> 5, lane = tid & 31;
    int wm = warp >> 1, wn = warp & 1;

    const __nv_bfloat16* ah = g_ah + (size_t)m0 * 128;
    const __nv_bfloat16* al = g_al + (size_t)m0 * 128;
    const __nv_bfloat16* bh = g_w2h + (size_t)n0 * 128;
    const __nv_bfloat16* bl = g_w2l + (size_t)n0 * 128;

    float acc[2][8][4];
#pragma unroll
    for (int i = 0; i < 2; i++)
#pragma unroll
        for (int j = 0; j < 8; j++)
#pragma unroll
            for (int q = 0; q < 4; q++) acc[i][j][q] = 0.f;

    int li = lane & 7, lm = lane >> 3;
    int a_row = (lm & 1) * 8 + li, a_cb = (lm >> 1) * 16;
    int b_row = (lm >> 1) * 8 + li, b_cb = (lm & 1) * 16;

#define LOADS2(S, K0) do {                                                      \
        uint32_t sbs = sb + (S) * 32768;                                        \
        const __nv_bfloat16* srcs[4] = {ah, al, bh, bl};                        \
        _Pragma("unroll")                                                       \
        for (int tt = 0; tt < 4; tt++) {                                        \
            const __nv_bfloat16* src = srcs[tt];                                \
            _Pragma("unroll")                                                   \
            for (int it = 0; it < 2; it++) {                                    \
                int idx = tid + it * 256;                                       \
                int r = idx >> 2, c16 = idx & 3;                                \
                const void* g = src + (size_t)r * 128 + (K0) + c16 * 8;         \
                uint32_t bo = (uint32_t)((r << 6) | (c16 << 4));                \
                bo ^= (bo >> 3) & 0x30;                                         \
                CP16(sbs + tt * 8192 + bo, g);                                  \
            }                                                                   \
        }                                                                       \
    } while (0)

    LOADS2(0, 0);
    CPCOMMIT();

    for (int kc = 0; kc < 4; kc++) {
        int s = kc & 1;
        if (kc < 3) {
            LOADS2(s ^ 1, (kc + 1) * 32);
            CPCOMMIT();
            CPWAIT(1);
        } else {
            CPWAIT(0);
        }
        __syncthreads();

        uint32_t stg = sb + s * 32768;
#pragma unroll
        for (int ks = 0; ks < 2; ks++) {
            int kb = ks * 32;
            uint32_t afh[2][4], afl[2][4];
#pragma unroll
            for (int mi = 0; mi < 2; mi++) {
                int r = wm * 32 + mi * 16 + a_row;
                uint32_t cb = (uint32_t)(kb + a_cb);
                uint32_t off = (r << 6) + (cb ^ (((r >> 1) & 3) << 4));
                ldm4(afh[mi], stg + off);
                ldm4(afl[mi], stg + 8192 + off);
            }
            uint32_t bfr[4][4];
#pragma unroll
            for (int p = 0; p < 4; p++) {
                int r = wn * 64 + p * 16 + b_row;
                uint32_t cb = (uint32_t)(kb + b_cb);
                ldm4(bfr[p], stg + 16384 + (r << 6) + (cb ^ (((r >> 1) & 3) << 4)));
            }
#pragma unroll
            for (int mi = 0; mi < 2; mi++)
#pragma unroll
                for (int ni = 0; ni < 8; ni++) {
                    mma16816(acc[mi][ni], afh[mi],
                             bfr[ni >> 1][(ni & 1) * 2], bfr[ni >> 1][(ni & 1) * 2 + 1]);
                    mma16816(acc[mi][ni], afl[mi],
                             bfr[ni >> 1][(ni & 1) * 2], bfr[ni >> 1][(ni & 1) * 2 + 1]);
                }
#pragma unroll
            for (int p = 0; p < 4; p++) {
                int r = wn * 64 + p * 16 + b_row;
                uint32_t cb = (uint32_t)(kb + b_cb);
                ldm4(bfr[p], stg + 24576 + (r << 6) + (cb ^ (((r >> 1) & 3) << 4)));
            }
#pragma unroll
            for (int mi = 0; mi < 2; mi++)
#pragma unroll
                for (int ni = 0; ni < 8; ni++)
                    mma16816(acc[mi][ni], afh[mi],
                             bfr[ni >> 1][(ni & 1) * 2], bfr[ni >> 1][(ni & 1) * 2 + 1]);
        }
        __syncthreads();
    }
#undef LOADS2

    // epilogue: stage to smem, add weighted bias, transposed store
    float* ot  = (float*)smc;            // 128 x 129
    float* b2s = ot + 128 * 129;         // 8 x 128
    float* srw = b2s + 1024;             // 256
    int*   sre = (int*)(srw + 256);      // 256

    int g = lane >> 2, tg = lane & 3;
#pragma unroll
    for (int mi = 0; mi < 2; mi++) {
        int rl = wm * 32 + mi * 16 + g;
#pragma unroll
        for (int ni = 0; ni < 8; ni++) {
            int cl = wn * 64 + ni * 8 + tg * 2;
            ot[rl * 129 + cl] = acc[mi][ni][0];
            ot[rl * 129 + cl + 1] = acc[mi][ni][1];
            ot[(rl + 8) * 129 + cl] = acc[mi][ni][2];
            ot[(rl + 8) * 129 + cl + 1] = acc[mi][ni][3];
        }
    }
    if (tid < 256) {
        sre[tid] = g_re[m0 * 2 + tid];
        srw[tid] = g_rw[m0 * 2 + tid];
    }
    for (int i = tid; i < 1024; i += 256) {
        int e = i >> 7, cl = i & 127;
        b2s[i] = b2[e * CC + n0 + cl];
    }
    __syncthreads();

    int c = tid >> 1, half = tid & 1;
    int batch = m0 >> 12, nb = m0 & (NNN - 1);
    float* ob = out + (size_t)batch * CC * NNN + (size_t)(n0 + c) * NNN + nb + half * 64;
#pragma unroll 2
    for (int tt4 = 0; tt4 < 64; tt4 += 4) {
        float4 v;
        float vv[4];
#pragma unroll
        for (int q = 0; q < 4; q++) {
            int ti = half * 64 + tt4 + q;
            float val = ot[ti * 129 + c];
            int ee0 = sre[2 * ti], ee1 = sre[2 * ti + 1];
            val += srw[2 * ti] * b2s[ee0 * 128 + c] + srw[2 * ti + 1] * b2s[ee1 * 128 + c];
            vv[q] = val;
        }
        v.x = vv[0]; v.y = vv[1]; v.z = vv[2]; v.w = vv[3];
        *(float4*)(ob + tt4) = v;
    }
}

// ---------------- load-balance loss -------------------------------------------
__global__ void k_lb(float* __restrict__ out, long long out_size) {
    if (threadIdx.x == 0 && out_size > (long long)BB * CC * NNN) {
        float s = 0.f;
#pragma unroll
        for (int e = 0; e < EE; e++) {
            float u = g_usage[e] * (1.0f / TT);
            s += u * u;
        }
        out[(size_t)BB * CC * NNN] = s * (float)EE;
    }
}

// ---------------- launch --------------------------------------------------------
extern "C" void kernel_launch(void* const* d_in, const int* in_sizes, int n_in,
                              void* d_out, int out_size) {
    const float* x     = (const float*)d_in[0];
    const float* wg1   = (const float*)d_in[1];
    const float* bg1   = (const float*)d_in[2];
    const float* gamma = (const float*)d_in[3];
    const float* beta  = (const float*)d_in[4];
    const float* wg2   = (const float*)d_in[5];
    const float* bg2   = (const float*)d_in[6];
    const float* w1    = (const float*)d_in[7];
    const float* b1    = (const float*)d_in[8];
    const float* w2    = (const float*)d_in[9];
    const float* b2    = (const float*)d_in[10];
    float* out = (float*)d_out;

    cudaFuncSetAttribute(k_gg,     cudaFuncAttributeMaxDynamicSharedMemorySize, GGSMEM);
    cudaFuncSetAttribute(k_egemm2, cudaFuncAttributeMaxDynamicSharedMemorySize, ESMEM2);

    k_zero<<<1, 512>>>();
    {
        long long tot4 = ((long long)TT * CC + (long long)CC * CC) / 4;
        int nb = (int)((tot4 + 255) / 256);
        k_split<<<nb, 256>>>(x, wg1);
    }
    k_split2<<<512, 256>>>(w1, w2);
    k_gg<<<1280, 256, GGSMEM>>>(bg1, b1);
    k_route<<<TT / 32, 256>>>(gamma, beta, wg2, bg2);
    k_fix<<<256, 256>>>(x, wg1, gamma, beta, wg2, bg2);
    k_scale<<<TT * 128 / 4 / 256, 256>>>();
    dim3 g2(CC / 128, TT / 128);
    k_egemm2<<<g2, 256, ESMEM2>>>(b2, out);
    k_lb<<<1, 32>>>(out, (long long)out_size);
}